// round 11
// baseline (speedup 1.0000x reference)
#include <cuda_runtime.h>
#include <cuda_fp16.h>
#include <stdint.h>
#include <math.h>

// ---------------- problem constants ----------------
#define DD 1024
#define EE 8
#define MM 4096
#define GG 8
#define CAP 256
#define NTOK 8192
#define ROWS_E 2048
#define SLOTS 16384

// GEMM tiling: CTA BMx128, 8 warps, BK=64, 3 stages, SW128
#define BN 128
#define BK 64
#define STAGES 3

#define SWZ128(o) ((o) ^ (((o) >> 3) & 0x70))

// ---------------- device scratch (static, allocation-free) ----------------
__device__ __align__(1024) float g_gates[NTOK * EE];
__device__ __align__(1024) int   g_tok_e[NTOK * 2];
__device__ __align__(1024) float g_tok_g[NTOK * 2];
__device__ __align__(1024) int   g_tok_slot[NTOK * 2];
__device__ __align__(1024) int   g_slot_token[SLOTS];
__device__ __align__(1024) float g_cv2[GG];
__device__ __align__(1024) __half g_xe[(size_t)SLOTS * DD];
__device__ __align__(1024) __half g_w1t[(size_t)EE * MM * DD];    // [E][M][D]
__device__ __align__(1024) __half g_w2t[(size_t)EE * DD * MM];    // [E][D][M]
__device__ __align__(1024) __half g_h[(size_t)SLOTS * MM];
__device__ __align__(1024) float g_ye[(size_t)SLOTS * DD];

// ---------------- PTX helpers (baseline PTX only) ----------------
__device__ __forceinline__ uint32_t smem_u32(const void* p) {
    uint32_t a;
    asm("{ .reg .u64 t; cvta.to.shared.u64 t, %1; cvt.u32.u64 %0, t; }"
        : "=r"(a) : "l"(p));
    return a;
}
#define CP16(dst, src) \
    asm volatile("cp.async.cg.shared.global [%0], [%1], 16;\n" :: "r"(dst), "l"(src))
#define CP_COMMIT() asm volatile("cp.async.commit_group;\n" ::: "memory")
#define CP_WAIT1()  asm volatile("cp.async.wait_group 1;\n" ::: "memory")
#define CP_WAIT0()  asm volatile("cp.async.wait_group 0;\n" ::: "memory")

__device__ __forceinline__ void ldsm4(uint32_t* r, uint32_t addr) {
    asm volatile("ldmatrix.sync.aligned.m8n8.x4.shared.b16 {%0,%1,%2,%3}, [%4];"
                 : "=r"(r[0]), "=r"(r[1]), "=r"(r[2]), "=r"(r[3]) : "r"(addr));
}
__device__ __forceinline__ void mma16816(float* d, const uint32_t* a,
                                         uint32_t b0, uint32_t b1) {
    asm volatile(
        "mma.sync.aligned.m16n8k16.row.col.f32.f16.f16.f32 "
        "{%0,%1,%2,%3}, {%4,%5,%6,%7}, {%8,%9}, {%0,%1,%2,%3};"
        : "+f"(d[0]), "+f"(d[1]), "+f"(d[2]), "+f"(d[3])
        : "r"(a[0]), "r"(a[1]), "r"(a[2]), "r"(a[3]), "r"(b0), "r"(b1));
}

// ---------------- router ----------------
__global__ void router_kernel(const float* __restrict__ x,
                              const float* __restrict__ wr) {
    int gwarp = (blockIdx.x * blockDim.x + threadIdx.x) >> 5;
    int lane = threadIdx.x & 31;
    if (gwarp >= NTOK) return;
    const float* xr = x + (size_t)gwarp * DD;
    float acc[EE];
#pragma unroll
    for (int e = 0; e < EE; e++) acc[e] = 0.f;
    for (int d = lane; d < DD; d += 32) {
        float xv = __ldg(xr + d);
        const float4* w4 = (const float4*)(wr + (size_t)d * EE);
        float4 w0 = __ldg(w4);
        float4 w1 = __ldg(w4 + 1);
        acc[0] = fmaf(xv, w0.x, acc[0]); acc[1] = fmaf(xv, w0.y, acc[1]);
        acc[2] = fmaf(xv, w0.z, acc[2]); acc[3] = fmaf(xv, w0.w, acc[3]);
        acc[4] = fmaf(xv, w1.x, acc[4]); acc[5] = fmaf(xv, w1.y, acc[5]);
        acc[6] = fmaf(xv, w1.z, acc[6]); acc[7] = fmaf(xv, w1.w, acc[7]);
    }
#pragma unroll
    for (int off = 16; off > 0; off >>= 1)
#pragma unroll
        for (int e = 0; e < EE; e++)
            acc[e] += __shfl_down_sync(0xffffffffu, acc[e], off);
    if (lane == 0) {
        float mx = acc[0];
#pragma unroll
        for (int e = 1; e < EE; e++) mx = fmaxf(mx, acc[e]);
        float gv[EE], s = 0.f;
#pragma unroll
        for (int e = 0; e < EE; e++) { gv[e] = expf(acc[e] - mx); s += gv[e]; }
        float inv = 1.f / s;
#pragma unroll
        for (int e = 0; e < EE; e++) { gv[e] *= inv; g_gates[gwarp * EE + e] = gv[e]; }
        int i0 = 0;
#pragma unroll
        for (int e = 1; e < EE; e++) if (acc[e] > acc[i0]) i0 = e;
        int i1 = (i0 == 0) ? 1 : 0;
#pragma unroll
        for (int e = 0; e < EE; e++) if (e != i0 && acc[e] > acc[i1]) i1 = e;
        g_tok_e[gwarp * 2 + 0] = i0;
        g_tok_e[gwarp * 2 + 1] = i1;
        g_tok_g[gwarp * 2 + 0] = gv[i0];
        g_tok_g[gwarp * 2 + 1] = gv[i1];
    }
}

// ---------------- importance / aux loss ----------------
__global__ void imp_kernel() {
    int g = blockIdx.x;
    int tid = threadIdx.x;
    float acc[EE];
#pragma unroll
    for (int e = 0; e < EE; e++) acc[e] = 0.f;
    for (int t = tid; t < 1024; t += 256) {
        const float* gp = g_gates + (size_t)(g * 1024 + t) * EE;
#pragma unroll
        for (int e = 0; e < EE; e++) acc[e] += gp[e];
    }
    __shared__ float sh[EE][256];
#pragma unroll
    for (int e = 0; e < EE; e++) sh[e][tid] = acc[e];
    __syncthreads();
    for (int off = 128; off > 0; off >>= 1) {
        if (tid < off)
#pragma unroll
            for (int e = 0; e < EE; e++) sh[e][tid] += sh[e][tid + off];
        __syncthreads();
    }
    if (tid == 0) {
        float mean = 0.f;
#pragma unroll
        for (int e = 0; e < EE; e++) mean += sh[e][0];
        mean *= (1.f / EE);
        float var = 0.f;
#pragma unroll
        for (int e = 0; e < EE; e++) { float d = sh[e][0] - mean; var += d * d; }
        var *= (1.f / EE);
        g_cv2[g] = var / (mean * mean);
    }
}

__global__ void aux_kernel(float* __restrict__ out) {
    float s = 0.f;
#pragma unroll
    for (int g = 0; g < GG; g++) s += g_cv2[g];
    out[(size_t)NTOK * DD] = s * (1.f / GG);
}

// ---------------- ballot-based deterministic capacity scan ----------------
__global__ void scan_kernel() {
    int g = blockIdx.x;
    int t = threadIdx.x;          // 1024
    int w = t >> 5, lane = t & 31;
    int tg = g * 1024 + t;
    int e0 = g_tok_e[tg * 2 + 0];
    int e1 = g_tok_e[tg * 2 + 1];
    __shared__ int warpcnt[32][8];
    __shared__ int warpbase[32][8];
    __shared__ int tot0[8];
    __shared__ int filled[8];
    unsigned lt = (1u << lane) - 1u;
    unsigned m[8];

    // pass k=0
#pragma unroll
    for (int e = 0; e < 8; e++) m[e] = __ballot_sync(0xffffffffu, e0 == e);
    if (lane < 8) warpcnt[w][lane] = __popc(m[lane]);
    int intra0 = __popc(m[e0] & lt);
    __syncthreads();
    if (t < 256) {
        int e = t >> 5, wi = lane;
        int val = warpcnt[wi][e];
        int incl = val;
#pragma unroll
        for (int off = 1; off < 32; off <<= 1) {
            int n = __shfl_up_sync(0xffffffffu, incl, off);
            if (wi >= off) incl += n;
        }
        warpbase[wi][e] = incl - val;
        if (wi == 31) tot0[e] = incl;
    }
    __syncthreads();
    int pos0 = warpbase[w][e0] + intra0;
    __syncthreads();

    // pass k=1 (offset by k=0 totals)
#pragma unroll
    for (int e = 0; e < 8; e++) m[e] = __ballot_sync(0xffffffffu, e1 == e);
    if (lane < 8) warpcnt[w][lane] = __popc(m[lane]);
    int intra1 = __popc(m[e1] & lt);
    __syncthreads();
    if (t < 256) {
        int e = t >> 5, wi = lane;
        int val = warpcnt[wi][e];
        int incl = val;
#pragma unroll
        for (int off = 1; off < 32; off <<= 1) {
            int n = __shfl_up_sync(0xffffffffu, incl, off);
            if (wi >= off) incl += n;
        }
        warpbase[wi][e] = incl - val;
        if (wi == 31) filled[e] = min(tot0[e] + incl, CAP);
    }
    __syncthreads();
    int pos1 = tot0[e1] + warpbase[w][e1] + intra1;

    int slot0 = (pos0 < CAP) ? pos0 : -1;
    int slot1 = (pos1 < CAP) ? pos1 : -1;
    g_tok_slot[tg * 2 + 0] = slot0;
    g_tok_slot[tg * 2 + 1] = slot1;
    if (slot0 >= 0) g_slot_token[(e0 * GG + g) * CAP + slot0] = tg;
    if (slot1 >= 0) g_slot_token[(e1 * GG + g) * CAP + slot1] = tg;
    __syncthreads();
    for (int idx = t; idx < EE * CAP; idx += 1024) {
        int e = idx / CAP, c = idx % CAP;
        if (c >= filled[e]) g_slot_token[(e * GG + g) * CAP + c] = -1;
    }
}

// ---------------- gather tokens -> fp16 expert buffers ----------------
__global__ void gather_kernel(const float* __restrict__ x) {
    int s_id = blockIdx.x;
    int tok = g_slot_token[s_id];
    int t = threadIdx.x;  // 128
    __half* dst = g_xe + (size_t)s_id * DD;
    if (tok >= 0) {
        const float4* src = (const float4*)(x + (size_t)tok * DD);
        float4 a = src[2 * t], b = src[2 * t + 1];
        __half h8[8];
        h8[0] = __float2half(a.x); h8[1] = __float2half(a.y);
        h8[2] = __float2half(a.z); h8[3] = __float2half(a.w);
        h8[4] = __float2half(b.x); h8[5] = __float2half(b.y);
        h8[6] = __float2half(b.z); h8[7] = __float2half(b.w);
        ((uint4*)dst)[t] = *(uint4*)h8;
    } else {
        ((uint4*)dst)[t] = make_uint4(0, 0, 0, 0);
    }
}

// -------- weight transpose + fp16 convert: in[e][R][C] -> out[e][C][R] -----
template <int R, int C>
__global__ void transpose_half_kernel(const float* __restrict__ in,
                                      __half* __restrict__ out) {
    __shared__ float tile[32][66];
    int e = blockIdx.z;
    int rb = blockIdx.y * 64, cb = blockIdx.x * 32;
    const float* ip = in + (size_t)e * R * C;
    __half* op = out + (size_t)e * C * R;
    int tx = threadIdx.x, ty = threadIdx.y;  // 32 x 8
#pragma unroll
    for (int j = 0; j < 8; j++) {
        int r = ty + j * 8;
        tile[tx][r] = ip[(size_t)(rb + r) * C + cb + tx];
    }
    __syncthreads();
#pragma unroll
    for (int j = 0; j < 4; j++) {
        int oc = ty + j * 8;
        float2 v = *(const float2*)&tile[oc][2 * tx];
        *(__half2*)&op[(size_t)(cb + oc) * R + rb + 2 * tx] =
            __floats2half2_rn(v.x, v.y);
    }
}

// ---------------- fast tanh-gelu ----------------
__device__ __forceinline__ float gelu_f(float v) {
    float u = 0.7978845608028654f * (v + 0.044715f * v * v * v);
    float ex = __expf(2.f * u);
    float th = 1.f - 2.f / (ex + 1.f);
    return 0.5f * v * (1.f + th);
}

// ------------- stage loader: A BMx64 + B 128x64 fp16, SW128 swizzle --------
template <int BM_T>
__device__ __forceinline__ void load_stage(uint32_t st,
                                           const __half* __restrict__ Ae,
                                           const __half* __restrict__ Be,
                                           int kc, int K, int tid) {
    constexpr int AJ = BM_T / 32;   // A CP16 per thread (256 thr, 8 chunks/row)
#pragma unroll
    for (int j = 0; j < AJ; j++) {
        int v = tid + j * 256;
        int row = v >> 3, c = v & 7;
        uint32_t off = SWZ128((uint32_t)(row * 128 + c * 16));
        CP16(st + off, Ae + (size_t)row * K + kc + c * 8);
    }
#pragma unroll
    for (int j = 0; j < 4; j++) {
        int v = tid + j * 256;
        int row = v >> 3, c = v & 7;
        uint32_t off = SWZ128((uint32_t)(row * 128 + c * 16));
        CP16(st + (uint32_t)(BM_T * 128) + off, Be + (size_t)row * K + kc + c * 8);
    }
}

// ------------- HMMA GEMM: C[BMx128] = A[BMxK] * B[128xK]^T + bias ----------
// 8 warps: 2 over M (BM/2 rows each) x 4 over N (32 cols each), BK=64.
template <int K_DIM, int BM_T, bool GELU>
__global__ void __launch_bounds__(256, 2)
hmma_gemm_kernel(const __half* __restrict__ A, const __half* __restrict__ B,
                 const float* __restrict__ bias, void* __restrict__ Cout,
                 int Ntot) {
    constexpr int NC = K_DIM / BK;
    constexpr int MI = BM_T / 32;                 // m16 frags per warp
    constexpr int STG = (BM_T + BN) * BK * 2;     // stage bytes
    extern __shared__ char smem[];
    __shared__ float bs[BN];
    const uint32_t sb = smem_u32(smem);
    const int tid = threadIdx.x;
    const int lane = tid & 31;
    const int wid = tid >> 5;
    const int wm = wid & 1;        // 2 warps over M
    const int wn = wid >> 1;       // 4 warps over N (32 cols each)
    const int e = blockIdx.z;
    const int m0 = blockIdx.y * BM_T;
    const int n0 = blockIdx.x * BN;

    const __half* Ae = A + ((size_t)(e * ROWS_E + m0)) * K_DIM;
    const __half* Be = B + ((size_t)e * Ntot + n0) * K_DIM;

    if (tid < BN) bs[tid] = __ldg(bias + (size_t)e * Ntot + n0 + tid);

    const int l15 = lane & 15;
    const int l16 = lane >> 4;
    uint32_t aAddr[MI], bAddr[2];
#pragma unroll
    for (int mi = 0; mi < MI; mi++)
        aAddr[mi] = sb + SWZ128((uint32_t)((wm * (BM_T / 2) + mi * 16 + l15) * 128 + l16 * 16));
#pragma unroll
    for (int ni = 0; ni < 2; ni++)
        bAddr[ni] = sb + (uint32_t)(BM_T * 128) +
                    SWZ128((uint32_t)((wn * 32 + ni * 16 + l15) * 128 + l16 * 16));

    float acc[MI][4][4];
#pragma unroll
    for (int i = 0; i < MI; i++)
#pragma unroll
        for (int j = 0; j < 4; j++)
#pragma unroll
            for (int k = 0; k < 4; k++) acc[i][j][k] = 0.f;

    // prologue: 2 stages
    load_stage<BM_T>(sb, Ae, Be, 0, K_DIM, tid);
    CP_COMMIT();
    load_stage<BM_T>(sb + STG, Ae, Be, BK, K_DIM, tid);
    CP_COMMIT();

#pragma unroll 1
    for (int i = 0; i < NC; i++) {
        CP_WAIT1();
        __syncthreads();
        {
            int nx = i + 2;
            if (nx < NC) {
                int sx = nx % STAGES;
                load_stage<BM_T>(sb + (uint32_t)sx * STG, Ae, Be, nx * BK, K_DIM, tid);
            }
        }
        CP_COMMIT();

        const uint32_t so = (uint32_t)(i % STAGES) * STG;
#pragma unroll
        for (int ks = 0; ks < 4; ks++) {
            const uint32_t xv = (uint32_t)ks * 32u;   // toggles addr bits [6:5]
            uint32_t a[MI][4], bb[2][4];
#pragma unroll
            for (int mi = 0; mi < MI; mi++) ldsm4(a[mi], (aAddr[mi] + so) ^ xv);
#pragma unroll
            for (int ni = 0; ni < 2; ni++) ldsm4(bb[ni], (bAddr[ni] + so) ^ xv);
#pragma unroll
            for (int mi = 0; mi < MI; mi++) {
#pragma unroll
                for (int f = 0; f < 4; f++) {
                    int ni = f >> 1, ss = f & 1;
                    mma16816(acc[mi][f], a[mi], bb[ni][ss], bb[ni][ss + 2]);
                }
            }
        }
    }
    // drain async copies and release pipeline smem for epilogue staging
    CP_WAIT0();
    __syncthreads();

    // ---------------- smem-staged epilogue ----------------
    const int rbase = wm * (BM_T / 2) + (lane >> 2);
    if (GELU) {
        __half* sC = (__half*)smem;          // [BM_T][136] halfs (272B stride)
#pragma unroll
        for (int mi = 0; mi < MI; mi++) {
#pragma unroll
            for (int f = 0; f < 4; f++) {
                int cidx = wn * 32 + (f >> 1) * 16 + (f & 1) * 8 + (lane & 3) * 2;
                float b0v = bs[cidx], b1v = bs[cidx + 1];
                int r0 = rbase + mi * 16;
                *(__half2*)&sC[r0 * 136 + cidx] = __floats2half2_rn(
                    gelu_f(acc[mi][f][0] + b0v), gelu_f(acc[mi][f][1] + b1v));
                *(__half2*)&sC[(r0 + 8) * 136 + cidx] = __floats2half2_rn(
                    gelu_f(acc[mi][f][2] + b0v), gelu_f(acc[mi][f][3] + b1v));
            }
        }
        __syncthreads();
        __half* Ch = (__half*)Cout;
        // BM_T rows x 16 segments x 8 halfs (16B) = 128 cols per row
        for (int v = tid; v < BM_T * 16; v += 256) {
            int row = v >> 4, seg = v & 15;
            *(uint4*)(Ch + (size_t)(e * ROWS_E + m0 + row) * Ntot + n0 + seg * 8) =
                *(const uint4*)&sC[row * 136 + seg * 8];
        }
    } else {
        float* sF = (float*)smem;            // [BM_T/2][132] floats per pass
        float* Cf = (float*)Cout;
#pragma unroll
        for (int p = 0; p < 2; p++) {
            if (wm == p) {
#pragma unroll
                for (int mi = 0; mi < MI; mi++) {
#pragma unroll
                    for (int f = 0; f < 4; f++) {
                        int cidx = wn * 32 + (f >> 1) * 16 + (f & 1) * 8 + (lane & 3) * 2;
                        float b0v = bs[cidx], b1v = bs[cidx + 1];
                        int r0l = (lane >> 2) + mi * 16;
                        *(float2*)&sF[r0l * 132 + cidx] =
                            make_float2(acc[mi][f][0] + b0v, acc[mi][f][1] + b1v);
                        *(float2*)&sF[(r0l + 8) * 132 + cidx] =
                            make_float2(acc[mi][f][2] + b0v, acc[mi][f][3] + b1v);
                    }
                }
            }
            __syncthreads();
            // (BM_T/2) rows x 32 segments x 4 floats (16B) = 128 cols per row
            for (int v = tid; v < (BM_T / 2) * 32; v += 256) {
                int row = v >> 5, seg = v & 31;
                *(uint4*)(Cf + (size_t)(e * ROWS_E + m0 + p * (BM_T / 2) + row) * Ntot +
                          n0 + seg * 4) = *(const uint4*)&sF[row * 132 + seg * 4];
            }
            __syncthreads();
        }
    }
}

// ---------------- weighted combine ----------------
__global__ void combine_kernel(float* __restrict__ out) {
    int tg = blockIdx.x;
    int g = tg >> 10;
    float4 acc = make_float4(0.f, 0.f, 0.f, 0.f);
#pragma unroll
    for (int k = 0; k < 2; k++) {
        int slot = g_tok_slot[tg * 2 + k];
        if (slot >= 0) {
            int e = g_tok_e[tg * 2 + k];
            float gv = g_tok_g[tg * 2 + k];
            const float4* row =
                (const float4*)(g_ye + ((size_t)(e * GG + g) * CAP + slot) * DD);
            float4 v = row[threadIdx.x];
            acc.x = fmaf(gv, v.x, acc.x);
            acc.y = fmaf(gv, v.y, acc.y);
            acc.z = fmaf(gv, v.z, acc.z);
            acc.w = fmaf(gv, v.w, acc.w);
        }
    }
    ((float4*)(out + (size_t)tg * DD))[threadIdx.x] = acc;
}

// ---------------- launch ----------------
extern "C" void kernel_launch(void* const* d_in, const int* in_sizes, int n_in,
                              void* d_out, int out_size) {
    const float* x  = (const float*)d_in[0];
    const float* wr = (const float*)d_in[1];
    const float* w1 = (const float*)d_in[2];
    const float* b1 = (const float*)d_in[3];
    const float* w2 = (const float*)d_in[4];
    const float* b2 = (const float*)d_in[5];
    float* out = (float*)d_out;

    __half *xe, *w1t, *w2t, *h;
    float* ye;
    cudaGetSymbolAddress((void**)&xe, g_xe);
    cudaGetSymbolAddress((void**)&w1t, g_w1t);
    cudaGetSymbolAddress((void**)&w2t, g_w2t);
    cudaGetSymbolAddress((void**)&h, g_h);
    cudaGetSymbolAddress((void**)&ye, g_ye);

    // stage bytes: GEMM1 (BM=128): 32KB x3 = 96KB; GEMM2 (BM=64): 24KB x3 = 72KB
    const int SMEM1 = STAGES * (128 + BN) * BK * 2;
    const int SMEM2 = STAGES * (64 + BN) * BK * 2;
    cudaFuncSetAttribute(hmma_gemm_kernel<1024, 128, true>,
                         cudaFuncAttributeMaxDynamicSharedMemorySize, SMEM1);
    cudaFuncSetAttribute(hmma_gemm_kernel<4096, 64, false>,
                         cudaFuncAttributeMaxDynamicSharedMemorySize, SMEM2);

    router_kernel<<<NTOK / 8, 256>>>(x, wr);
    imp_kernel<<<GG, 256>>>();
    if (out_size > NTOK * DD) aux_kernel<<<1, 1>>>(out);
    scan_kernel<<<GG, 1024>>>();
    gather_kernel<<<SLOTS, 128>>>(x);

    // w1 [E][D=1024][M=4096] -> w1t [E][M][D] fp16
    transpose_half_kernel<1024, 4096>
        <<<dim3(4096 / 32, 1024 / 64, EE), dim3(32, 8)>>>(w1, w1t);
    // w2 [E][M=4096][D=1024] -> w2t [E][D][M] fp16
    transpose_half_kernel<4096, 1024>
        <<<dim3(1024 / 32, 4096 / 64, EE), dim3(32, 8)>>>(w2, w2t);

    // h = gelu(xe @ w1 + b1): per expert 2048 x 4096, K=1024 (BM=128)
    hmma_gemm_kernel<1024, 128, true>
        <<<dim3(MM / BN, ROWS_E / 128, EE), 256, SMEM1>>>(
            xe, w1t, b1, h, MM);
    // ye = h @ w2 + b2: per expert 2048 x 1024, K=4096 (BM=64 -> 2048 CTAs)
    hmma_gemm_kernel<4096, 64, false>
        <<<dim3(DD / BN, ROWS_E / 64, EE), 256, SMEM2>>>(
            h, w2t, b2, ye, DD);

    combine_kernel<<<NTOK, 256>>>(out);
}

// round 12
// speedup vs baseline: 1.0299x; 1.0299x over previous
#include <cuda_runtime.h>
#include <cuda_fp16.h>
#include <stdint.h>
#include <math.h>

// ---------------- problem constants ----------------
#define DD 1024
#define EE 8
#define MM 4096
#define GG 8
#define CAP 256
#define NTOK 8192
#define ROWS_E 2048
#define SLOTS 16384

// GEMM tiling: CTA 128x128, 8 warps of 64x32, BK=64, 3 stages, SW128
#define BN 128
#define BK 64
#define STAGES 3

#define SWZ128(o) ((o) ^ (((o) >> 3) & 0x70))

// ---------------- device scratch (static, allocation-free) ----------------
__device__ __align__(1024) float g_gates[NTOK * EE];
__device__ __align__(1024) int   g_tok_e[NTOK * 2];
__device__ __align__(1024) float g_tok_g[NTOK * 2];
__device__ __align__(1024) int   g_tok_slot[NTOK * 2];
__device__ __align__(1024) int   g_slot_token[SLOTS];
__device__ __align__(1024) float g_cv2[GG];
__device__ __align__(1024) __half g_xe[(size_t)SLOTS * DD];
__device__ __align__(1024) __half g_w1t[(size_t)EE * MM * DD];    // [E][M][D]
__device__ __align__(1024) __half g_w2t[(size_t)EE * DD * MM];    // [E][D][M]
__device__ __align__(1024) __half g_h[(size_t)SLOTS * MM];
__device__ __align__(1024) float g_ye[(size_t)SLOTS * DD];        // K-slice 0
__device__ __align__(1024) float g_ye2[(size_t)SLOTS * DD];       // K-slice 1

// ---------------- PTX helpers (baseline PTX only) ----------------
__device__ __forceinline__ uint32_t smem_u32(const void* p) {
    uint32_t a;
    asm("{ .reg .u64 t; cvta.to.shared.u64 t, %1; cvt.u32.u64 %0, t; }"
        : "=r"(a) : "l"(p));
    return a;
}
#define CP16(dst, src) \
    asm volatile("cp.async.cg.shared.global [%0], [%1], 16;\n" :: "r"(dst), "l"(src))
#define CP_COMMIT() asm volatile("cp.async.commit_group;\n" ::: "memory")
#define CP_WAIT1()  asm volatile("cp.async.wait_group 1;\n" ::: "memory")
#define CP_WAIT0()  asm volatile("cp.async.wait_group 0;\n" ::: "memory")

__device__ __forceinline__ void ldsm4(uint32_t* r, uint32_t addr) {
    asm volatile("ldmatrix.sync.aligned.m8n8.x4.shared.b16 {%0,%1,%2,%3}, [%4];"
                 : "=r"(r[0]), "=r"(r[1]), "=r"(r[2]), "=r"(r[3]) : "r"(addr));
}
__device__ __forceinline__ void mma16816(float* d, const uint32_t* a,
                                         uint32_t b0, uint32_t b1) {
    asm volatile(
        "mma.sync.aligned.m16n8k16.row.col.f32.f16.f16.f32 "
        "{%0,%1,%2,%3}, {%4,%5,%6,%7}, {%8,%9}, {%0,%1,%2,%3};"
        : "+f"(d[0]), "+f"(d[1]), "+f"(d[2]), "+f"(d[3])
        : "r"(a[0]), "r"(a[1]), "r"(a[2]), "r"(a[3]), "r"(b0), "r"(b1));
}

// ---------------- router ----------------
__global__ void router_kernel(const float* __restrict__ x,
                              const float* __restrict__ wr) {
    int gwarp = (blockIdx.x * blockDim.x + threadIdx.x) >> 5;
    int lane = threadIdx.x & 31;
    if (gwarp >= NTOK) return;
    const float* xr = x + (size_t)gwarp * DD;
    float acc[EE];
#pragma unroll
    for (int e = 0; e < EE; e++) acc[e] = 0.f;
    for (int d = lane; d < DD; d += 32) {
        float xv = __ldg(xr + d);
        const float4* w4 = (const float4*)(wr + (size_t)d * EE);
        float4 w0 = __ldg(w4);
        float4 w1 = __ldg(w4 + 1);
        acc[0] = fmaf(xv, w0.x, acc[0]); acc[1] = fmaf(xv, w0.y, acc[1]);
        acc[2] = fmaf(xv, w0.z, acc[2]); acc[3] = fmaf(xv, w0.w, acc[3]);
        acc[4] = fmaf(xv, w1.x, acc[4]); acc[5] = fmaf(xv, w1.y, acc[5]);
        acc[6] = fmaf(xv, w1.z, acc[6]); acc[7] = fmaf(xv, w1.w, acc[7]);
    }
#pragma unroll
    for (int off = 16; off > 0; off >>= 1)
#pragma unroll
        for (int e = 0; e < EE; e++)
            acc[e] += __shfl_down_sync(0xffffffffu, acc[e], off);
    if (lane == 0) {
        float mx = acc[0];
#pragma unroll
        for (int e = 1; e < EE; e++) mx = fmaxf(mx, acc[e]);
        float gv[EE], s = 0.f;
#pragma unroll
        for (int e = 0; e < EE; e++) { gv[e] = expf(acc[e] - mx); s += gv[e]; }
        float inv = 1.f / s;
#pragma unroll
        for (int e = 0; e < EE; e++) { gv[e] *= inv; g_gates[gwarp * EE + e] = gv[e]; }
        int i0 = 0;
#pragma unroll
        for (int e = 1; e < EE; e++) if (acc[e] > acc[i0]) i0 = e;
        int i1 = (i0 == 0) ? 1 : 0;
#pragma unroll
        for (int e = 0; e < EE; e++) if (e != i0 && acc[e] > acc[i1]) i1 = e;
        g_tok_e[gwarp * 2 + 0] = i0;
        g_tok_e[gwarp * 2 + 1] = i1;
        g_tok_g[gwarp * 2 + 0] = gv[i0];
        g_tok_g[gwarp * 2 + 1] = gv[i1];
    }
}

// ---------------- importance / aux loss ----------------
__global__ void imp_kernel() {
    int g = blockIdx.x;
    int tid = threadIdx.x;
    float acc[EE];
#pragma unroll
    for (int e = 0; e < EE; e++) acc[e] = 0.f;
    for (int t = tid; t < 1024; t += 256) {
        const float* gp = g_gates + (size_t)(g * 1024 + t) * EE;
#pragma unroll
        for (int e = 0; e < EE; e++) acc[e] += gp[e];
    }
    __shared__ float sh[EE][256];
#pragma unroll
    for (int e = 0; e < EE; e++) sh[e][tid] = acc[e];
    __syncthreads();
    for (int off = 128; off > 0; off >>= 1) {
        if (tid < off)
#pragma unroll
            for (int e = 0; e < EE; e++) sh[e][tid] += sh[e][tid + off];
        __syncthreads();
    }
    if (tid == 0) {
        float mean = 0.f;
#pragma unroll
        for (int e = 0; e < EE; e++) mean += sh[e][0];
        mean *= (1.f / EE);
        float var = 0.f;
#pragma unroll
        for (int e = 0; e < EE; e++) { float d = sh[e][0] - mean; var += d * d; }
        var *= (1.f / EE);
        g_cv2[g] = var / (mean * mean);
    }
}

__global__ void aux_kernel(float* __restrict__ out) {
    float s = 0.f;
#pragma unroll
    for (int g = 0; g < GG; g++) s += g_cv2[g];
    out[(size_t)NTOK * DD] = s * (1.f / GG);
}

// ---------------- ballot-based deterministic capacity scan ----------------
__global__ void scan_kernel() {
    int g = blockIdx.x;
    int t = threadIdx.x;          // 1024
    int w = t >> 5, lane = t & 31;
    int tg = g * 1024 + t;
    int e0 = g_tok_e[tg * 2 + 0];
    int e1 = g_tok_e[tg * 2 + 1];
    __shared__ int warpcnt[32][8];
    __shared__ int warpbase[32][8];
    __shared__ int tot0[8];
    __shared__ int filled[8];
    unsigned lt = (1u << lane) - 1u;
    unsigned m[8];

    // pass k=0
#pragma unroll
    for (int e = 0; e < 8; e++) m[e] = __ballot_sync(0xffffffffu, e0 == e);
    if (lane < 8) warpcnt[w][lane] = __popc(m[lane]);
    int intra0 = __popc(m[e0] & lt);
    __syncthreads();
    if (t < 256) {
        int e = t >> 5, wi = lane;
        int val = warpcnt[wi][e];
        int incl = val;
#pragma unroll
        for (int off = 1; off < 32; off <<= 1) {
            int n = __shfl_up_sync(0xffffffffu, incl, off);
            if (wi >= off) incl += n;
        }
        warpbase[wi][e] = incl - val;
        if (wi == 31) tot0[e] = incl;
    }
    __syncthreads();
    int pos0 = warpbase[w][e0] + intra0;
    __syncthreads();

    // pass k=1 (offset by k=0 totals)
#pragma unroll
    for (int e = 0; e < 8; e++) m[e] = __ballot_sync(0xffffffffu, e1 == e);
    if (lane < 8) warpcnt[w][lane] = __popc(m[lane]);
    int intra1 = __popc(m[e1] & lt);
    __syncthreads();
    if (t < 256) {
        int e = t >> 5, wi = lane;
        int val = warpcnt[wi][e];
        int incl = val;
#pragma unroll
        for (int off = 1; off < 32; off <<= 1) {
            int n = __shfl_up_sync(0xffffffffu, incl, off);
            if (wi >= off) incl += n;
        }
        warpbase[wi][e] = incl - val;
        if (wi == 31) filled[e] = min(tot0[e] + incl, CAP);
    }
    __syncthreads();
    int pos1 = tot0[e1] + warpbase[w][e1] + intra1;

    int slot0 = (pos0 < CAP) ? pos0 : -1;
    int slot1 = (pos1 < CAP) ? pos1 : -1;
    g_tok_slot[tg * 2 + 0] = slot0;
    g_tok_slot[tg * 2 + 1] = slot1;
    if (slot0 >= 0) g_slot_token[(e0 * GG + g) * CAP + slot0] = tg;
    if (slot1 >= 0) g_slot_token[(e1 * GG + g) * CAP + slot1] = tg;
    __syncthreads();
    for (int idx = t; idx < EE * CAP; idx += 1024) {
        int e = idx / CAP, c = idx % CAP;
        if (c >= filled[e]) g_slot_token[(e * GG + g) * CAP + c] = -1;
    }
}

// ---------------- gather tokens -> fp16 expert buffers ----------------
__global__ void gather_kernel(const float* __restrict__ x) {
    int s_id = blockIdx.x;
    int tok = g_slot_token[s_id];
    int t = threadIdx.x;  // 128
    __half* dst = g_xe + (size_t)s_id * DD;
    if (tok >= 0) {
        const float4* src = (const float4*)(x + (size_t)tok * DD);
        float4 a = src[2 * t], b = src[2 * t + 1];
        __half h8[8];
        h8[0] = __float2half(a.x); h8[1] = __float2half(a.y);
        h8[2] = __float2half(a.z); h8[3] = __float2half(a.w);
        h8[4] = __float2half(b.x); h8[5] = __float2half(b.y);
        h8[6] = __float2half(b.z); h8[7] = __float2half(b.w);
        ((uint4*)dst)[t] = *(uint4*)h8;
    } else {
        ((uint4*)dst)[t] = make_uint4(0, 0, 0, 0);
    }
}

// -------- weight transpose + fp16 convert: in[e][R][C] -> out[e][C][R] -----
template <int R, int C>
__global__ void transpose_half_kernel(const float* __restrict__ in,
                                      __half* __restrict__ out) {
    __shared__ float tile[32][66];
    int e = blockIdx.z;
    int rb = blockIdx.y * 64, cb = blockIdx.x * 32;
    const float* ip = in + (size_t)e * R * C;
    __half* op = out + (size_t)e * C * R;
    int tx = threadIdx.x, ty = threadIdx.y;  // 32 x 8
#pragma unroll
    for (int j = 0; j < 8; j++) {
        int r = ty + j * 8;
        tile[tx][r] = ip[(size_t)(rb + r) * C + cb + tx];
    }
    __syncthreads();
#pragma unroll
    for (int j = 0; j < 4; j++) {
        int oc = ty + j * 8;
        float2 v = *(const float2*)&tile[oc][2 * tx];
        *(__half2*)&op[(size_t)(cb + oc) * R + rb + 2 * tx] =
            __floats2half2_rn(v.x, v.y);
    }
}

// ---------------- fast tanh-gelu ----------------
__device__ __forceinline__ float gelu_f(float v) {
    float u = 0.7978845608028654f * (v + 0.044715f * v * v * v);
    float ex = __expf(2.f * u);
    float th = 1.f - 2.f / (ex + 1.f);
    return 0.5f * v * (1.f + th);
}

// ------------- stage loader: A 128x64 + B 128x64 fp16, SW128 swizzle -------
__device__ __forceinline__ void load_stage(uint32_t st,
                                           const __half* __restrict__ Ae,
                                           const __half* __restrict__ Be,
                                           int kc, int K, int tid) {
#pragma unroll
    for (int j = 0; j < 4; j++) {
        int v = tid + j * 256;
        int row = v >> 3, c = v & 7;
        uint32_t off = SWZ128((uint32_t)(row * 128 + c * 16));
        CP16(st + off, Ae + (size_t)row * K + kc + c * 8);
    }
#pragma unroll
    for (int j = 0; j < 4; j++) {
        int v = tid + j * 256;
        int row = v >> 3, c = v & 7;
        uint32_t off = SWZ128((uint32_t)(row * 128 + c * 16));
        CP16(st + 16384u + off, Be + (size_t)row * K + kc + c * 8);
    }
}

// ------- HMMA GEMM: C[128x128] = A[128xK_LEN] * B[128xK_LEN]^T (+bias) -----
// 8 warps of 64x32. KSPLIT>1: blockIdx.z = e*KSPLIT+slice; slice s computes
// K range [s*K_LEN, (s+1)*K_LEN) and writes to Cout_s; bias only in slice 0.
template <int K_STRIDE, int K_LEN, int KSPLIT, bool GELU>
__global__ void __launch_bounds__(256, 2)
hmma_gemm_kernel(const __half* __restrict__ A, const __half* __restrict__ B,
                 const float* __restrict__ bias, void* __restrict__ Cout0,
                 void* __restrict__ Cout1, int Ntot) {
    constexpr int NC = K_LEN / BK;
    constexpr int STG = (128 + BN) * BK * 2;   // 32 KB
    extern __shared__ char smem[];
    __shared__ float bs[BN];
    const uint32_t sb = smem_u32(smem);
    const int tid = threadIdx.x;
    const int lane = tid & 31;
    const int wid = tid >> 5;
    const int wm = wid & 1;        // 2 warps over M (64 rows each)
    const int wn = wid >> 1;       // 4 warps over N (32 cols each)
    const int ez = blockIdx.z;
    const int e = ez / KSPLIT;
    const int slice = ez % KSPLIT;
    const int koff = slice * K_LEN;
    void* Cout = slice ? Cout1 : Cout0;
    const int m0 = blockIdx.y * 128;
    const int n0 = blockIdx.x * BN;

    const __half* Ae = A + ((size_t)(e * ROWS_E + m0)) * K_STRIDE + koff;
    const __half* Be = B + ((size_t)e * Ntot + n0) * K_STRIDE + koff;

    if (tid < BN)
        bs[tid] = (slice == 0) ? __ldg(bias + (size_t)e * Ntot + n0 + tid) : 0.f;

    const int l15 = lane & 15;
    const int l16 = lane >> 4;
    uint32_t aAddr[4], bAddr[2];
#pragma unroll
    for (int mi = 0; mi < 4; mi++)
        aAddr[mi] = sb + SWZ128((uint32_t)((wm * 64 + mi * 16 + l15) * 128 + l16 * 16));
#pragma unroll
    for (int ni = 0; ni < 2; ni++)
        bAddr[ni] = sb + 16384u +
                    SWZ128((uint32_t)((wn * 32 + ni * 16 + l15) * 128 + l16 * 16));

    float acc[4][4][4];
#pragma unroll
    for (int i = 0; i < 4; i++)
#pragma unroll
        for (int j = 0; j < 4; j++)
#pragma unroll
            for (int k = 0; k < 4; k++) acc[i][j][k] = 0.f;

    // prologue: 2 stages
    load_stage(sb, Ae, Be, 0, K_STRIDE, tid);
    CP_COMMIT();
    load_stage(sb + STG, Ae, Be, BK, K_STRIDE, tid);
    CP_COMMIT();

#pragma unroll 1
    for (int i = 0; i < NC; i++) {
        CP_WAIT1();
        __syncthreads();
        {
            int nx = i + 2;
            if (nx < NC) {
                int sx = nx % STAGES;
                load_stage(sb + (uint32_t)sx * STG, Ae, Be, nx * BK, K_STRIDE, tid);
            }
        }
        CP_COMMIT();

        const uint32_t so = (uint32_t)(i % STAGES) * STG;
#pragma unroll
        for (int ks = 0; ks < 4; ks++) {
            const uint32_t xv = (uint32_t)ks * 32u;   // toggles addr bits [6:5]
            uint32_t a[4][4], bb[2][4];
#pragma unroll
            for (int mi = 0; mi < 4; mi++) ldsm4(a[mi], (aAddr[mi] + so) ^ xv);
#pragma unroll
            for (int ni = 0; ni < 2; ni++) ldsm4(bb[ni], (bAddr[ni] + so) ^ xv);
#pragma unroll
            for (int mi = 0; mi < 4; mi++) {
#pragma unroll
                for (int f = 0; f < 4; f++) {
                    int ni = f >> 1, ss = f & 1;
                    mma16816(acc[mi][f], a[mi], bb[ni][ss], bb[ni][ss + 2]);
                }
            }
        }
    }
    // drain async copies and release pipeline smem for epilogue staging
    CP_WAIT0();
    __syncthreads();

    // ---------------- smem-staged epilogue ----------------
    const int rbase = wm * 64 + (lane >> 2);
    if (GELU) {
        __half* sC = (__half*)smem;          // [128][136] halfs (272B stride)
#pragma unroll
        for (int mi = 0; mi < 4; mi++) {
#pragma unroll
            for (int f = 0; f < 4; f++) {
                int cidx = wn * 32 + (f >> 1) * 16 + (f & 1) * 8 + (lane & 3) * 2;
                float b0v = bs[cidx], b1v = bs[cidx + 1];
                int r0 = rbase + mi * 16;
                *(__half2*)&sC[r0 * 136 + cidx] = __floats2half2_rn(
                    gelu_f(acc[mi][f][0] + b0v), gelu_f(acc[mi][f][1] + b1v));
                *(__half2*)&sC[(r0 + 8) * 136 + cidx] = __floats2half2_rn(
                    gelu_f(acc[mi][f][2] + b0v), gelu_f(acc[mi][f][3] + b1v));
            }
        }
        __syncthreads();
        __half* Ch = (__half*)Cout;
        // 128 rows x 16 segments x 8 halfs (16B) = 128 cols per row
        for (int v = tid; v < 128 * 16; v += 256) {
            int row = v >> 4, seg = v & 15;
            *(uint4*)(Ch + (size_t)(e * ROWS_E + m0 + row) * Ntot + n0 + seg * 8) =
                *(const uint4*)&sC[row * 136 + seg * 8];
        }
    } else {
        float* sF = (float*)smem;            // [64][132] floats (528B stride)
        float* Cf = (float*)Cout;
#pragma unroll
        for (int p = 0; p < 2; p++) {
            if (wm == p) {
#pragma unroll
                for (int mi = 0; mi < 4; mi++) {
#pragma unroll
                    for (int f = 0; f < 4; f++) {
                        int cidx = wn * 32 + (f >> 1) * 16 + (f & 1) * 8 + (lane & 3) * 2;
                        float b0v = bs[cidx], b1v = bs[cidx + 1];
                        int r0l = (lane >> 2) + mi * 16;
                        *(float2*)&sF[r0l * 132 + cidx] =
                            make_float2(acc[mi][f][0] + b0v, acc[mi][f][1] + b1v);
                        *(float2*)&sF[(r0l + 8) * 132 + cidx] =
                            make_float2(acc[mi][f][2] + b0v, acc[mi][f][3] + b1v);
                    }
                }
            }
            __syncthreads();
            // 64 rows x 32 segments x 4 floats (16B) = 128 cols per row
            for (int v = tid; v < 64 * 32; v += 256) {
                int row = v >> 5, seg = v & 31;
                *(uint4*)(Cf + (size_t)(e * ROWS_E + m0 + p * 64 + row) * Ntot +
                          n0 + seg * 4) = *(const uint4*)&sF[row * 132 + seg * 4];
            }
            __syncthreads();
        }
    }
}

// ---------------- weighted combine (sums the two K-slice partials) --------
__global__ void combine_kernel(float* __restrict__ out) {
    int tg = blockIdx.x;
    int g = tg >> 10;
    float4 acc = make_float4(0.f, 0.f, 0.f, 0.f);
#pragma unroll
    for (int k = 0; k < 2; k++) {
        int slot = g_tok_slot[tg * 2 + k];
        if (slot >= 0) {
            int e = g_tok_e[tg * 2 + k];
            float gv = g_tok_g[tg * 2 + k];
            size_t off = ((size_t)(e * GG + g) * CAP + slot) * DD;
            const float4* row0 = (const float4*)(g_ye + off);
            const float4* row1 = (const float4*)(g_ye2 + off);
            float4 v0 = row0[threadIdx.x];
            float4 v1 = row1[threadIdx.x];
            acc.x = fmaf(gv, v0.x + v1.x, acc.x);
            acc.y = fmaf(gv, v0.y + v1.y, acc.y);
            acc.z = fmaf(gv, v0.z + v1.z, acc.z);
            acc.w = fmaf(gv, v0.w + v1.w, acc.w);
        }
    }
    ((float4*)(out + (size_t)tg * DD))[threadIdx.x] = acc;
}

// ---------------- launch ----------------
extern "C" void kernel_launch(void* const* d_in, const int* in_sizes, int n_in,
                              void* d_out, int out_size) {
    const float* x  = (const float*)d_in[0];
    const float* wr = (const float*)d_in[1];
    const float* w1 = (const float*)d_in[2];
    const float* b1 = (const float*)d_in[3];
    const float* w2 = (const float*)d_in[4];
    const float* b2 = (const float*)d_in[5];
    float* out = (float*)d_out;

    __half *xe, *w1t, *w2t, *h;
    float *ye, *ye2;
    cudaGetSymbolAddress((void**)&xe, g_xe);
    cudaGetSymbolAddress((void**)&w1t, g_w1t);
    cudaGetSymbolAddress((void**)&w2t, g_w2t);
    cudaGetSymbolAddress((void**)&h, g_h);
    cudaGetSymbolAddress((void**)&ye, g_ye);
    cudaGetSymbolAddress((void**)&ye2, g_ye2);

    const int SMEM_GEMM = STAGES * (128 + BN) * BK * 2;   // 96 KB
    cudaFuncSetAttribute(hmma_gemm_kernel<1024, 1024, 1, true>,
                         cudaFuncAttributeMaxDynamicSharedMemorySize, SMEM_GEMM);
    cudaFuncSetAttribute(hmma_gemm_kernel<4096, 2048, 2, false>,
                         cudaFuncAttributeMaxDynamicSharedMemorySize, SMEM_GEMM);

    router_kernel<<<NTOK / 8, 256>>>(x, wr);
    imp_kernel<<<GG, 256>>>();
    if (out_size > NTOK * DD) aux_kernel<<<1, 1>>>(out);
    scan_kernel<<<GG, 1024>>>();
    gather_kernel<<<SLOTS, 128>>>(x);

    // w1 [E][D=1024][M=4096] -> w1t [E][M][D] fp16
    transpose_half_kernel<1024, 4096>
        <<<dim3(4096 / 32, 1024 / 64, EE), dim3(32, 8)>>>(w1, w1t);
    // w2 [E][M=4096][D=1024] -> w2t [E][D][M] fp16
    transpose_half_kernel<4096, 1024>
        <<<dim3(1024 / 32, 4096 / 64, EE), dim3(32, 8)>>>(w2, w2t);

    // h = gelu(xe @ w1 + b1): per expert 2048 x 4096, K=1024 (4096 CTAs)
    hmma_gemm_kernel<1024, 1024, 1, true>
        <<<dim3(MM / BN, ROWS_E / 128, EE), 256, SMEM_GEMM>>>(
            xe, w1t, b1, h, nullptr, MM);
    // ye = h @ w2 + b2: per expert 2048 x 1024, K=4096 split into 2 slices
    // of K=2048 -> one launch of 2048 CTAs (6.92 waves, tail 92% full)
    hmma_gemm_kernel<4096, 2048, 2, false>
        <<<dim3(DD / BN, ROWS_E / 128, EE * 2), 256, SMEM_GEMM>>>(
            h, w2t, b2, ye, ye2, DD);

    combine_kernel<<<NTOK, 256>>>(out);
}

// round 13
// speedup vs baseline: 1.0420x; 1.0117x over previous
#include <cuda_runtime.h>
#include <cuda_fp16.h>
#include <stdint.h>
#include <math.h>

// ---------------- problem constants ----------------
#define DD 1024
#define EE 8
#define MM 4096
#define GG 8
#define CAP 256
#define NTOK 8192
#define ROWS_E 2048
#define SLOTS 16384

// GEMM tiling: CTA 128x128, 8 warps of 64x32, BK=64, 3 stages, SW128
#define BM 128
#define BN 128
#define BK 64
#define STAGES 3
#define STAGE_B 32768          // A 128x64 fp16 (16KB) + B 128x64 fp16 (16KB)
#define SMEM_GEMM (STAGES * STAGE_B)   // 98304

#define SWZ128(o) ((o) ^ (((o) >> 3) & 0x70))

// ---------------- device scratch (static, allocation-free) ----------------
__device__ __align__(1024) float g_gates[NTOK * EE];
__device__ __align__(1024) int   g_tok_e[NTOK * 2];
__device__ __align__(1024) float g_tok_g[NTOK * 2];
__device__ __align__(1024) int   g_tok_slot[NTOK * 2];
__device__ __align__(1024) int   g_slot_token[SLOTS];
__device__ __align__(1024) float g_cv2[GG];
__device__ __align__(1024) __half g_xe[(size_t)SLOTS * DD];
__device__ __align__(1024) __half g_w1t[(size_t)EE * MM * DD];    // [E][M][D]
__device__ __align__(1024) __half g_w2t[(size_t)EE * DD * MM];    // [E][D][M]
__device__ __align__(1024) __half g_h[(size_t)SLOTS * MM];
__device__ __align__(1024) float g_ye[(size_t)SLOTS * DD];

// ---------------- PTX helpers (baseline PTX only) ----------------
__device__ __forceinline__ uint32_t smem_u32(const void* p) {
    uint32_t a;
    asm("{ .reg .u64 t; cvta.to.shared.u64 t, %1; cvt.u32.u64 %0, t; }"
        : "=r"(a) : "l"(p));
    return a;
}
#define CP16(dst, src) \
    asm volatile("cp.async.cg.shared.global [%0], [%1], 16;\n" :: "r"(dst), "l"(src))
#define CP_COMMIT() asm volatile("cp.async.commit_group;\n" ::: "memory")
#define CP_WAIT1()  asm volatile("cp.async.wait_group 1;\n" ::: "memory")
#define CP_WAIT0()  asm volatile("cp.async.wait_group 0;\n" ::: "memory")

__device__ __forceinline__ void ldsm4(uint32_t* r, uint32_t addr) {
    asm volatile("ldmatrix.sync.aligned.m8n8.x4.shared.b16 {%0,%1,%2,%3}, [%4];"
                 : "=r"(r[0]), "=r"(r[1]), "=r"(r[2]), "=r"(r[3]) : "r"(addr));
}
__device__ __forceinline__ void mma16816(float* d, const uint32_t* a,
                                         uint32_t b0, uint32_t b1) {
    asm volatile(
        "mma.sync.aligned.m16n8k16.row.col.f32.f16.f16.f32 "
        "{%0,%1,%2,%3}, {%4,%5,%6,%7}, {%8,%9}, {%0,%1,%2,%3};"
        : "+f"(d[0]), "+f"(d[1]), "+f"(d[2]), "+f"(d[3])
        : "r"(a[0]), "r"(a[1]), "r"(a[2]), "r"(a[3]), "r"(b0), "r"(b1));
}

// ---------------- router ----------------
__global__ void router_kernel(const float* __restrict__ x,
                              const float* __restrict__ wr) {
    int gwarp = (blockIdx.x * blockDim.x + threadIdx.x) >> 5;
    int lane = threadIdx.x & 31;
    if (gwarp >= NTOK) return;
    const float* xr = x + (size_t)gwarp * DD;
    float acc[EE];
#pragma unroll
    for (int e = 0; e < EE; e++) acc[e] = 0.f;
    for (int d = lane; d < DD; d += 32) {
        float xv = __ldg(xr + d);
        const float4* w4 = (const float4*)(wr + (size_t)d * EE);
        float4 w0 = __ldg(w4);
        float4 w1 = __ldg(w4 + 1);
        acc[0] = fmaf(xv, w0.x, acc[0]); acc[1] = fmaf(xv, w0.y, acc[1]);
        acc[2] = fmaf(xv, w0.z, acc[2]); acc[3] = fmaf(xv, w0.w, acc[3]);
        acc[4] = fmaf(xv, w1.x, acc[4]); acc[5] = fmaf(xv, w1.y, acc[5]);
        acc[6] = fmaf(xv, w1.z, acc[6]); acc[7] = fmaf(xv, w1.w, acc[7]);
    }
#pragma unroll
    for (int off = 16; off > 0; off >>= 1)
#pragma unroll
        for (int e = 0; e < EE; e++)
            acc[e] += __shfl_down_sync(0xffffffffu, acc[e], off);
    if (lane == 0) {
        float mx = acc[0];
#pragma unroll
        for (int e = 1; e < EE; e++) mx = fmaxf(mx, acc[e]);
        float gv[EE], s = 0.f;
#pragma unroll
        for (int e = 0; e < EE; e++) { gv[e] = expf(acc[e] - mx); s += gv[e]; }
        float inv = 1.f / s;
#pragma unroll
        for (int e = 0; e < EE; e++) { gv[e] *= inv; g_gates[gwarp * EE + e] = gv[e]; }
        int i0 = 0;
#pragma unroll
        for (int e = 1; e < EE; e++) if (acc[e] > acc[i0]) i0 = e;
        int i1 = (i0 == 0) ? 1 : 0;
#pragma unroll
        for (int e = 0; e < EE; e++) if (e != i0 && acc[e] > acc[i1]) i1 = e;
        g_tok_e[gwarp * 2 + 0] = i0;
        g_tok_e[gwarp * 2 + 1] = i1;
        g_tok_g[gwarp * 2 + 0] = gv[i0];
        g_tok_g[gwarp * 2 + 1] = gv[i1];
    }
}

// ---------------- importance / aux loss ----------------
__global__ void imp_kernel() {
    int g = blockIdx.x;
    int tid = threadIdx.x;
    float acc[EE];
#pragma unroll
    for (int e = 0; e < EE; e++) acc[e] = 0.f;
    for (int t = tid; t < 1024; t += 256) {
        const float* gp = g_gates + (size_t)(g * 1024 + t) * EE;
#pragma unroll
        for (int e = 0; e < EE; e++) acc[e] += gp[e];
    }
    __shared__ float sh[EE][256];
#pragma unroll
    for (int e = 0; e < EE; e++) sh[e][tid] = acc[e];
    __syncthreads();
    for (int off = 128; off > 0; off >>= 1) {
        if (tid < off)
#pragma unroll
            for (int e = 0; e < EE; e++) sh[e][tid] += sh[e][tid + off];
        __syncthreads();
    }
    if (tid == 0) {
        float mean = 0.f;
#pragma unroll
        for (int e = 0; e < EE; e++) mean += sh[e][0];
        mean *= (1.f / EE);
        float var = 0.f;
#pragma unroll
        for (int e = 0; e < EE; e++) { float d = sh[e][0] - mean; var += d * d; }
        var *= (1.f / EE);
        g_cv2[g] = var / (mean * mean);
    }
}

__global__ void aux_kernel(float* __restrict__ out) {
    float s = 0.f;
#pragma unroll
    for (int g = 0; g < GG; g++) s += g_cv2[g];
    out[(size_t)NTOK * DD] = s * (1.f / GG);
}

// ---------------- ballot-based deterministic capacity scan ----------------
__global__ void scan_kernel() {
    int g = blockIdx.x;
    int t = threadIdx.x;          // 1024
    int w = t >> 5, lane = t & 31;
    int tg = g * 1024 + t;
    int e0 = g_tok_e[tg * 2 + 0];
    int e1 = g_tok_e[tg * 2 + 1];
    __shared__ int warpcnt[32][8];
    __shared__ int warpbase[32][8];
    __shared__ int tot0[8];
    __shared__ int filled[8];
    unsigned lt = (1u << lane) - 1u;
    unsigned m[8];

    // pass k=0
#pragma unroll
    for (int e = 0; e < 8; e++) m[e] = __ballot_sync(0xffffffffu, e0 == e);
    if (lane < 8) warpcnt[w][lane] = __popc(m[lane]);
    int intra0 = __popc(m[e0] & lt);
    __syncthreads();
    if (t < 256) {
        int e = t >> 5, wi = lane;
        int val = warpcnt[wi][e];
        int incl = val;
#pragma unroll
        for (int off = 1; off < 32; off <<= 1) {
            int n = __shfl_up_sync(0xffffffffu, incl, off);
            if (wi >= off) incl += n;
        }
        warpbase[wi][e] = incl - val;
        if (wi == 31) tot0[e] = incl;
    }
    __syncthreads();
    int pos0 = warpbase[w][e0] + intra0;
    __syncthreads();

    // pass k=1 (offset by k=0 totals)
#pragma unroll
    for (int e = 0; e < 8; e++) m[e] = __ballot_sync(0xffffffffu, e1 == e);
    if (lane < 8) warpcnt[w][lane] = __popc(m[lane]);
    int intra1 = __popc(m[e1] & lt);
    __syncthreads();
    if (t < 256) {
        int e = t >> 5, wi = lane;
        int val = warpcnt[wi][e];
        int incl = val;
#pragma unroll
        for (int off = 1; off < 32; off <<= 1) {
            int n = __shfl_up_sync(0xffffffffu, incl, off);
            if (wi >= off) incl += n;
        }
        warpbase[wi][e] = incl - val;
        if (wi == 31) filled[e] = min(tot0[e] + incl, CAP);
    }
    __syncthreads();
    int pos1 = tot0[e1] + warpbase[w][e1] + intra1;

    int slot0 = (pos0 < CAP) ? pos0 : -1;
    int slot1 = (pos1 < CAP) ? pos1 : -1;
    g_tok_slot[tg * 2 + 0] = slot0;
    g_tok_slot[tg * 2 + 1] = slot1;
    if (slot0 >= 0) g_slot_token[(e0 * GG + g) * CAP + slot0] = tg;
    if (slot1 >= 0) g_slot_token[(e1 * GG + g) * CAP + slot1] = tg;
    __syncthreads();
    for (int idx = t; idx < EE * CAP; idx += 1024) {
        int e = idx / CAP, c = idx % CAP;
        if (c >= filled[e]) g_slot_token[(e * GG + g) * CAP + c] = -1;
    }
}

// ---------------- gather tokens -> fp16 expert buffers ----------------
__global__ void gather_kernel(const float* __restrict__ x) {
    int s_id = blockIdx.x;
    int tok = g_slot_token[s_id];
    int t = threadIdx.x;  // 128
    __half* dst = g_xe + (size_t)s_id * DD;
    if (tok >= 0) {
        const float4* src = (const float4*)(x + (size_t)tok * DD);
        float4 a = src[2 * t], b = src[2 * t + 1];
        __half h8[8];
        h8[0] = __float2half(a.x); h8[1] = __float2half(a.y);
        h8[2] = __float2half(a.z); h8[3] = __float2half(a.w);
        h8[4] = __float2half(b.x); h8[5] = __float2half(b.y);
        h8[6] = __float2half(b.z); h8[7] = __float2half(b.w);
        ((uint4*)dst)[t] = *(uint4*)h8;
    } else {
        ((uint4*)dst)[t] = make_uint4(0, 0, 0, 0);
    }
}

// -------- weight transpose + fp16 convert: in[e][R][C] -> out[e][C][R] -----
template <int R, int C>
__global__ void transpose_half_kernel(const float* __restrict__ in,
                                      __half* __restrict__ out) {
    __shared__ float tile[32][66];
    int e = blockIdx.z;
    int rb = blockIdx.y * 64, cb = blockIdx.x * 32;
    const float* ip = in + (size_t)e * R * C;
    __half* op = out + (size_t)e * C * R;
    int tx = threadIdx.x, ty = threadIdx.y;  // 32 x 8
#pragma unroll
    for (int j = 0; j < 8; j++) {
        int r = ty + j * 8;
        tile[tx][r] = ip[(size_t)(rb + r) * C + cb + tx];
    }
    __syncthreads();
#pragma unroll
    for (int j = 0; j < 4; j++) {
        int oc = ty + j * 8;
        float2 v = *(const float2*)&tile[oc][2 * tx];
        *(__half2*)&op[(size_t)(cb + oc) * R + rb + 2 * tx] =
            __floats2half2_rn(v.x, v.y);
    }
}

// ---------------- fast tanh-gelu ----------------
__device__ __forceinline__ float gelu_f(float v) {
    float u = 0.7978845608028654f * (v + 0.044715f * v * v * v);
    float ex = __expf(2.f * u);
    float th = 1.f - 2.f / (ex + 1.f);
    return 0.5f * v * (1.f + th);
}

// ------------- stage loader: A 128x64 + B 128x64 fp16, SW128 swizzle -------
__device__ __forceinline__ void load_stage(uint32_t st,
                                           const __half* __restrict__ Ae,
                                           const __half* __restrict__ Be,
                                           int kc, int K, int tid) {
#pragma unroll
    for (int j = 0; j < 4; j++) {
        int v = tid + j * 256;
        int row = v >> 3, c = v & 7;
        uint32_t off = SWZ128((uint32_t)(row * 128 + c * 16));
        CP16(st + off, Ae + (size_t)row * K + kc + c * 8);
    }
#pragma unroll
    for (int j = 0; j < 4; j++) {
        int v = tid + j * 256;
        int row = v >> 3, c = v & 7;
        uint32_t off = SWZ128((uint32_t)(row * 128 + c * 16));
        CP16(st + 16384u + off, Be + (size_t)row * K + kc + c * 8);
    }
}

// ---------------- HMMA GEMM: C[128x128] = A[128xK] * B[128xK]^T + bias -----
// 8 warps of 64x32 (2 over M x 4 over N), BK=64 (4 k16 steps per stage).
// Next-stage cp.async is issued AFTER ks=0's ldsm so MMA starts right after
// the barrier and the copy burst hides under tensor work.
template <int K_DIM, bool GELU>
__global__ void __launch_bounds__(256, 2)
hmma_gemm_kernel(const __half* __restrict__ A, const __half* __restrict__ B,
                 const float* __restrict__ bias, void* __restrict__ Cout,
                 int Ntot) {
    constexpr int NC = K_DIM / BK;
    extern __shared__ char smem[];
    __shared__ float bs[BN];
    const uint32_t sb = smem_u32(smem);
    const int tid = threadIdx.x;
    const int lane = tid & 31;
    const int wid = tid >> 5;
    const int wm = wid & 1;        // 2 warps over M (64 rows each)
    const int wn = wid >> 1;       // 4 warps over N (32 cols each)
    const int e = blockIdx.z;
    const int m0 = blockIdx.y * BM;
    const int n0 = blockIdx.x * BN;

    const __half* Ae = A + ((size_t)(e * ROWS_E + m0)) * K_DIM;
    const __half* Be = B + ((size_t)e * Ntot + n0) * K_DIM;

    if (tid < BN) bs[tid] = __ldg(bias + (size_t)e * Ntot + n0 + tid);

    const int l15 = lane & 15;
    const int l16 = lane >> 4;
    uint32_t aAddr[4], bAddr[2];
#pragma unroll
    for (int mi = 0; mi < 4; mi++)
        aAddr[mi] = sb + SWZ128((uint32_t)((wm * 64 + mi * 16 + l15) * 128 + l16 * 16));
#pragma unroll
    for (int ni = 0; ni < 2; ni++)
        bAddr[ni] = sb + 16384u +
                    SWZ128((uint32_t)((wn * 32 + ni * 16 + l15) * 128 + l16 * 16));

    float acc[4][4][4];
#pragma unroll
    for (int i = 0; i < 4; i++)
#pragma unroll
        for (int j = 0; j < 4; j++)
#pragma unroll
            for (int k = 0; k < 4; k++) acc[i][j][k] = 0.f;

    // prologue: 2 stages
    load_stage(sb, Ae, Be, 0, K_DIM, tid);
    CP_COMMIT();
    load_stage(sb + STAGE_B, Ae, Be, BK, K_DIM, tid);
    CP_COMMIT();

#pragma unroll 1
    for (int i = 0; i < NC; i++) {
        CP_WAIT1();
        __syncthreads();

        const uint32_t so = (uint32_t)(i % STAGES) * STAGE_B;
#pragma unroll
        for (int ks = 0; ks < 4; ks++) {
            const uint32_t xv = (uint32_t)ks * 32u;   // toggles addr bits [6:5]
            uint32_t a[4][4], bb[2][4];
#pragma unroll
            for (int mi = 0; mi < 4; mi++) ldsm4(a[mi], (aAddr[mi] + so) ^ xv);
#pragma unroll
            for (int ni = 0; ni < 2; ni++) ldsm4(bb[ni], (bAddr[ni] + so) ^ xv);

            if (ks == 0) {
                // issue next-stage loads in the shadow of this iteration's MMAs
                int nx = i + 2;
                if (nx < NC) {
                    int sx = nx % STAGES;
                    load_stage(sb + (uint32_t)sx * STAGE_B, Ae, Be,
                               nx * BK, K_DIM, tid);
                }
                CP_COMMIT();
            }

#pragma unroll
            for (int mi = 0; mi < 4; mi++) {
#pragma unroll
                for (int f = 0; f < 4; f++) {
                    int ni = f >> 1, ss = f & 1;
                    mma16816(acc[mi][f], a[mi], bb[ni][ss], bb[ni][ss + 2]);
                }
            }
        }
    }
    // drain async copies and release pipeline smem for epilogue staging
    CP_WAIT0();
    __syncthreads();

    // ---------------- smem-staged epilogue ----------------
    const int rbase = wm * 64 + (lane >> 2);
    if (GELU) {
        __half* sC = (__half*)smem;          // [128][136] halfs (272B stride)
#pragma unroll
        for (int mi = 0; mi < 4; mi++) {
#pragma unroll
            for (int f = 0; f < 4; f++) {
                int cidx = wn * 32 + (f >> 1) * 16 + (f & 1) * 8 + (lane & 3) * 2;
                float b0v = bs[cidx], b1v = bs[cidx + 1];
                int r0 = rbase + mi * 16;
                *(__half2*)&sC[r0 * 136 + cidx] = __floats2half2_rn(
                    gelu_f(acc[mi][f][0] + b0v), gelu_f(acc[mi][f][1] + b1v));
                *(__half2*)&sC[(r0 + 8) * 136 + cidx] = __floats2half2_rn(
                    gelu_f(acc[mi][f][2] + b0v), gelu_f(acc[mi][f][3] + b1v));
            }
        }
        __syncthreads();
        __half* Ch = (__half*)Cout;
        // 128 rows x 16 segments x 8 halfs (16B) = 128 cols per row
        for (int v = tid; v < 128 * 16; v += 256) {
            int row = v >> 4, seg = v & 15;
            *(uint4*)(Ch + (size_t)(e * ROWS_E + m0 + row) * Ntot + n0 + seg * 8) =
                *(const uint4*)&sC[row * 136 + seg * 8];
        }
    } else {
        float* sF = (float*)smem;            // [64][132] floats (528B stride)
        float* Cf = (float*)Cout;
#pragma unroll
        for (int p = 0; p < 2; p++) {
            if (wm == p) {
#pragma unroll
                for (int mi = 0; mi < 4; mi++) {
#pragma unroll
                    for (int f = 0; f < 4; f++) {
                        int cidx = wn * 32 + (f >> 1) * 16 + (f & 1) * 8 + (lane & 3) * 2;
                        float b0v = bs[cidx], b1v = bs[cidx + 1];
                        int r0l = (lane >> 2) + mi * 16;
                        *(float2*)&sF[r0l * 132 + cidx] =
                            make_float2(acc[mi][f][0] + b0v, acc[mi][f][1] + b1v);
                        *(float2*)&sF[(r0l + 8) * 132 + cidx] =
                            make_float2(acc[mi][f][2] + b0v, acc[mi][f][3] + b1v);
                    }
                }
            }
            __syncthreads();
            // 64 rows x 32 segments x 4 floats (16B) = 128 cols per row
            for (int v = tid; v < 64 * 32; v += 256) {
                int row = v >> 5, seg = v & 31;
                *(uint4*)(Cf + (size_t)(e * ROWS_E + m0 + p * 64 + row) * Ntot +
                          n0 + seg * 4) = *(const uint4*)&sF[row * 132 + seg * 4];
            }
            __syncthreads();
        }
    }
}

// ---------------- weighted combine ----------------
__global__ void combine_kernel(float* __restrict__ out) {
    int tg = blockIdx.x;
    int g = tg >> 10;
    float4 acc = make_float4(0.f, 0.f, 0.f, 0.f);
#pragma unroll
    for (int k = 0; k < 2; k++) {
        int slot = g_tok_slot[tg * 2 + k];
        if (slot >= 0) {
            int e = g_tok_e[tg * 2 + k];
            float gv = g_tok_g[tg * 2 + k];
            const float4* row =
                (const float4*)(g_ye + ((size_t)(e * GG + g) * CAP + slot) * DD);
            float4 v = row[threadIdx.x];
            acc.x = fmaf(gv, v.x, acc.x);
            acc.y = fmaf(gv, v.y, acc.y);
            acc.z = fmaf(gv, v.z, acc.z);
            acc.w = fmaf(gv, v.w, acc.w);
        }
    }
    ((float4*)(out + (size_t)tg * DD))[threadIdx.x] = acc;
}

// ---------------- launch ----------------
extern "C" void kernel_launch(void* const* d_in, const int* in_sizes, int n_in,
                              void* d_out, int out_size) {
    const float* x  = (const float*)d_in[0];
    const float* wr = (const float*)d_in[1];
    const float* w1 = (const float*)d_in[2];
    const float* b1 = (const float*)d_in[3];
    const float* w2 = (const float*)d_in[4];
    const float* b2 = (const float*)d_in[5];
    float* out = (float*)d_out;

    __half *xe, *w1t, *w2t, *h;
    float* ye;
    cudaGetSymbolAddress((void**)&xe, g_xe);
    cudaGetSymbolAddress((void**)&w1t, g_w1t);
    cudaGetSymbolAddress((void**)&w2t, g_w2t);
    cudaGetSymbolAddress((void**)&h, g_h);
    cudaGetSymbolAddress((void**)&ye, g_ye);

    cudaFuncSetAttribute(hmma_gemm_kernel<1024, true>,
                         cudaFuncAttributeMaxDynamicSharedMemorySize, SMEM_GEMM);
    cudaFuncSetAttribute(hmma_gemm_kernel<4096, false>,
                         cudaFuncAttributeMaxDynamicSharedMemorySize, SMEM_GEMM);

    router_kernel<<<NTOK / 8, 256>>>(x, wr);
    imp_kernel<<<GG, 256>>>();
    if (out_size > NTOK * DD) aux_kernel<<<1, 1>>>(out);
    scan_kernel<<<GG, 1024>>>();
    gather_kernel<<<SLOTS, 128>>>(x);

    // w1 [E][D=1024][M=4096] -> w1t [E][M][D] fp16
    transpose_half_kernel<1024, 4096>
        <<<dim3(4096 / 32, 1024 / 64, EE), dim3(32, 8)>>>(w1, w1t);
    // w2 [E][M=4096][D=1024] -> w2t [E][D][M] fp16
    transpose_half_kernel<4096, 1024>
        <<<dim3(1024 / 32, 4096 / 64, EE), dim3(32, 8)>>>(w2, w2t);

    // h = gelu(xe @ w1 + b1): per expert 2048 x 4096, K=1024
    hmma_gemm_kernel<1024, true>
        <<<dim3(MM / BN, ROWS_E / BM, EE), 256, SMEM_GEMM>>>(
            xe, w1t, b1, h, MM);
    // ye = h @ w2 + b2: per expert 2048 x 1024, K=4096
    hmma_gemm_kernel<4096, false>
        <<<dim3(DD / BN, ROWS_E / BM, EE), 256, SMEM_GEMM>>>(
            h, w2t, b2, ye, DD);

    combine_kernel<<<NTOK, 256>>>(out);
}

// round 14
// speedup vs baseline: 1.0697x; 1.0266x over previous
#include <cuda_runtime.h>
#include <cuda_fp16.h>
#include <stdint.h>
#include <math.h>

// ---------------- problem constants ----------------
#define DD 1024
#define EE 8
#define MM 4096
#define GG 8
#define CAP 256
#define NTOK 8192
#define ROWS_E 2048
#define SLOTS 16384

// GEMM tiling: CTA 128x128, 8 warps of 64x32, BK=64, 3 stages, SW128 (R10)
#define BM 128
#define BN 128
#define BK 64
#define STAGES 3
#define STAGE_B 32768
#define SMEM_GEMM (STAGES * STAGE_B)   // 98304

#define SWZ128(o) ((o) ^ (((o) >> 3) & 0x70))

// ---------------- device scratch (static, allocation-free) ----------------
__device__ __align__(1024) float g_gates[NTOK * EE];
__device__ __align__(1024) int   g_tok_e[NTOK * 2];
__device__ __align__(1024) float g_tok_g[NTOK * 2];
__device__ __align__(1024) int   g_tok_slot[NTOK * 2];
__device__ __align__(1024) int   g_slot_token[SLOTS];
__device__ __align__(1024) float g_cv2[GG];
__device__ __align__(1024) __half g_xe[(size_t)SLOTS * DD];
__device__ __align__(1024) __half g_w1t[(size_t)EE * MM * DD];    // [E][M][D]
__device__ __align__(1024) __half g_w2t[(size_t)EE * DD * MM];    // [E][D][M]
__device__ __align__(1024) __half g_h[(size_t)SLOTS * MM];
__device__ __align__(1024) float g_ye[(size_t)SLOTS * DD];

// ---------------- PTX helpers (baseline PTX only) ----------------
__device__ __forceinline__ uint32_t smem_u32(const void* p) {
    uint32_t a;
    asm("{ .reg .u64 t; cvta.to.shared.u64 t, %1; cvt.u32.u64 %0, t; }"
        : "=r"(a) : "l"(p));
    return a;
}
#define CP16(dst, src) \
    asm volatile("cp.async.cg.shared.global [%0], [%1], 16;\n" :: "r"(dst), "l"(src))
#define CP_COMMIT() asm volatile("cp.async.commit_group;\n" ::: "memory")
#define CP_WAIT1()  asm volatile("cp.async.wait_group 1;\n" ::: "memory")
#define CP_WAIT0()  asm volatile("cp.async.wait_group 0;\n" ::: "memory")

__device__ __forceinline__ void ldsm4(uint32_t* r, uint32_t addr) {
    asm volatile("ldmatrix.sync.aligned.m8n8.x4.shared.b16 {%0,%1,%2,%3}, [%4];"
                 : "=r"(r[0]), "=r"(r[1]), "=r"(r[2]), "=r"(r[3]) : "r"(addr));
}
__device__ __forceinline__ void mma16816(float* d, const uint32_t* a,
                                         uint32_t b0, uint32_t b1) {
    asm volatile(
        "mma.sync.aligned.m16n8k16.row.col.f32.f16.f16.f32 "
        "{%0,%1,%2,%3}, {%4,%5,%6,%7}, {%8,%9}, {%0,%1,%2,%3};"
        : "+f"(d[0]), "+f"(d[1]), "+f"(d[2]), "+f"(d[3])
        : "r"(a[0]), "r"(a[1]), "r"(a[2]), "r"(a[3]), "r"(b0), "r"(b1));
}

// ---------------- router ----------------
__global__ void router_kernel(const float* __restrict__ x,
                              const float* __restrict__ wr) {
    int gwarp = (blockIdx.x * blockDim.x + threadIdx.x) >> 5;
    int lane = threadIdx.x & 31;
    if (gwarp >= NTOK) return;
    const float* xr = x + (size_t)gwarp * DD;
    float acc[EE];
#pragma unroll
    for (int e = 0; e < EE; e++) acc[e] = 0.f;
    for (int d = lane; d < DD; d += 32) {
        float xv = __ldg(xr + d);
        const float4* w4 = (const float4*)(wr + (size_t)d * EE);
        float4 w0 = __ldg(w4);
        float4 w1 = __ldg(w4 + 1);
        acc[0] = fmaf(xv, w0.x, acc[0]); acc[1] = fmaf(xv, w0.y, acc[1]);
        acc[2] = fmaf(xv, w0.z, acc[2]); acc[3] = fmaf(xv, w0.w, acc[3]);
        acc[4] = fmaf(xv, w1.x, acc[4]); acc[5] = fmaf(xv, w1.y, acc[5]);
        acc[6] = fmaf(xv, w1.z, acc[6]); acc[7] = fmaf(xv, w1.w, acc[7]);
    }
#pragma unroll
    for (int off = 16; off > 0; off >>= 1)
#pragma unroll
        for (int e = 0; e < EE; e++)
            acc[e] += __shfl_down_sync(0xffffffffu, acc[e], off);
    if (lane == 0) {
        float mx = acc[0];
#pragma unroll
        for (int e = 1; e < EE; e++) mx = fmaxf(mx, acc[e]);
        float gv[EE], s = 0.f;
#pragma unroll
        for (int e = 0; e < EE; e++) { gv[e] = expf(acc[e] - mx); s += gv[e]; }
        float inv = 1.f / s;
#pragma unroll
        for (int e = 0; e < EE; e++) { gv[e] *= inv; g_gates[gwarp * EE + e] = gv[e]; }
        int i0 = 0;
#pragma unroll
        for (int e = 1; e < EE; e++) if (acc[e] > acc[i0]) i0 = e;
        int i1 = (i0 == 0) ? 1 : 0;
#pragma unroll
        for (int e = 0; e < EE; e++) if (e != i0 && acc[e] > acc[i1]) i1 = e;
        g_tok_e[gwarp * 2 + 0] = i0;
        g_tok_e[gwarp * 2 + 1] = i1;
        g_tok_g[gwarp * 2 + 0] = gv[i0];
        g_tok_g[gwarp * 2 + 1] = gv[i1];
    }
}

// ---------------- importance / aux loss ----------------
__global__ void imp_kernel() {
    int g = blockIdx.x;
    int tid = threadIdx.x;
    float acc[EE];
#pragma unroll
    for (int e = 0; e < EE; e++) acc[e] = 0.f;
    for (int t = tid; t < 1024; t += 256) {
        const float* gp = g_gates + (size_t)(g * 1024 + t) * EE;
#pragma unroll
        for (int e = 0; e < EE; e++) acc[e] += gp[e];
    }
    __shared__ float sh[EE][256];
#pragma unroll
    for (int e = 0; e < EE; e++) sh[e][tid] = acc[e];
    __syncthreads();
    for (int off = 128; off > 0; off >>= 1) {
        if (tid < off)
#pragma unroll
            for (int e = 0; e < EE; e++) sh[e][tid] += sh[e][tid + off];
        __syncthreads();
    }
    if (tid == 0) {
        float mean = 0.f;
#pragma unroll
        for (int e = 0; e < EE; e++) mean += sh[e][0];
        mean *= (1.f / EE);
        float var = 0.f;
#pragma unroll
        for (int e = 0; e < EE; e++) { float d = sh[e][0] - mean; var += d * d; }
        var *= (1.f / EE);
        g_cv2[g] = var / (mean * mean);
    }
}

__global__ void aux_kernel(float* __restrict__ out) {
    float s = 0.f;
#pragma unroll
    for (int g = 0; g < GG; g++) s += g_cv2[g];
    out[(size_t)NTOK * DD] = s * (1.f / GG);
}

// ---------------- ballot-based deterministic capacity scan ----------------
__global__ void scan_kernel() {
    int g = blockIdx.x;
    int t = threadIdx.x;          // 1024
    int w = t >> 5, lane = t & 31;
    int tg = g * 1024 + t;
    int e0 = g_tok_e[tg * 2 + 0];
    int e1 = g_tok_e[tg * 2 + 1];
    __shared__ int warpcnt[32][8];
    __shared__ int warpbase[32][8];
    __shared__ int tot0[8];
    __shared__ int filled[8];
    unsigned lt = (1u << lane) - 1u;
    unsigned m[8];

#pragma unroll
    for (int e = 0; e < 8; e++) m[e] = __ballot_sync(0xffffffffu, e0 == e);
    if (lane < 8) warpcnt[w][lane] = __popc(m[lane]);
    int intra0 = __popc(m[e0] & lt);
    __syncthreads();
    if (t < 256) {
        int e = t >> 5, wi = lane;
        int val = warpcnt[wi][e];
        int incl = val;
#pragma unroll
        for (int off = 1; off < 32; off <<= 1) {
            int n = __shfl_up_sync(0xffffffffu, incl, off);
            if (wi >= off) incl += n;
        }
        warpbase[wi][e] = incl - val;
        if (wi == 31) tot0[e] = incl;
    }
    __syncthreads();
    int pos0 = warpbase[w][e0] + intra0;
    __syncthreads();

#pragma unroll
    for (int e = 0; e < 8; e++) m[e] = __ballot_sync(0xffffffffu, e1 == e);
    if (lane < 8) warpcnt[w][lane] = __popc(m[lane]);
    int intra1 = __popc(m[e1] & lt);
    __syncthreads();
    if (t < 256) {
        int e = t >> 5, wi = lane;
        int val = warpcnt[wi][e];
        int incl = val;
#pragma unroll
        for (int off = 1; off < 32; off <<= 1) {
            int n = __shfl_up_sync(0xffffffffu, incl, off);
            if (wi >= off) incl += n;
        }
        warpbase[wi][e] = incl - val;
        if (wi == 31) filled[e] = min(tot0[e] + incl, CAP);
    }
    __syncthreads();
    int pos1 = tot0[e1] + warpbase[w][e1] + intra1;

    int slot0 = (pos0 < CAP) ? pos0 : -1;
    int slot1 = (pos1 < CAP) ? pos1 : -1;
    g_tok_slot[tg * 2 + 0] = slot0;
    g_tok_slot[tg * 2 + 1] = slot1;
    if (slot0 >= 0) g_slot_token[(e0 * GG + g) * CAP + slot0] = tg;
    if (slot1 >= 0) g_slot_token[(e1 * GG + g) * CAP + slot1] = tg;
    __syncthreads();
    for (int idx = t; idx < EE * CAP; idx += 1024) {
        int e = idx / CAP, c = idx % CAP;
        if (c >= filled[e]) g_slot_token[(e * GG + g) * CAP + c] = -1;
    }
}

// ---------------- gather tokens -> fp16 expert buffers ----------------
__global__ void gather_kernel(const float* __restrict__ x) {
    int s_id = blockIdx.x;
    int tok = g_slot_token[s_id];
    int t = threadIdx.x;  // 128
    __half* dst = g_xe + (size_t)s_id * DD;
    if (tok >= 0) {
        const float4* src = (const float4*)(x + (size_t)tok * DD);
        float4 a = src[2 * t], b = src[2 * t + 1];
        __half h8[8];
        h8[0] = __float2half(a.x); h8[1] = __float2half(a.y);
        h8[2] = __float2half(a.z); h8[3] = __float2half(a.w);
        h8[4] = __float2half(b.x); h8[5] = __float2half(b.y);
        h8[6] = __float2half(b.z); h8[7] = __float2half(b.w);
        ((uint4*)dst)[t] = *(uint4*)h8;
    } else {
        ((uint4*)dst)[t] = make_uint4(0, 0, 0, 0);
    }
}

// -------- weight transpose + fp16 convert: in[e][R][C] -> out[e][C][R] -----
template <int R, int C>
__global__ void transpose_half_kernel(const float* __restrict__ in,
                                      __half* __restrict__ out) {
    __shared__ float tile[32][66];
    int e = blockIdx.z;
    int rb = blockIdx.y * 64, cb = blockIdx.x * 32;
    const float* ip = in + (size_t)e * R * C;
    __half* op = out + (size_t)e * C * R;
    int tx = threadIdx.x, ty = threadIdx.y;  // 32 x 8
#pragma unroll
    for (int j = 0; j < 8; j++) {
        int r = ty + j * 8;
        tile[tx][r] = ip[(size_t)(rb + r) * C + cb + tx];
    }
    __syncthreads();
#pragma unroll
    for (int j = 0; j < 4; j++) {
        int oc = ty + j * 8;
        float2 v = *(const float2*)&tile[oc][2 * tx];
        *(__half2*)&op[(size_t)(cb + oc) * R + rb + 2 * tx] =
            __floats2half2_rn(v.x, v.y);
    }
}

// ---------------- fast tanh-gelu ----------------
__device__ __forceinline__ float gelu_f(float v) {
    float u = 0.7978845608028654f * (v + 0.044715f * v * v * v);
    float ex = __expf(2.f * u);
    float th = 1.f - 2.f / (ex + 1.f);
    return 0.5f * v * (1.f + th);
}

// ------------- stage loader: A 128x64 + B 128x64 fp16, SW128 swizzle -------
__device__ __forceinline__ void load_stage(uint32_t st,
                                           const __half* __restrict__ Ae,
                                           const __half* __restrict__ Be,
                                           int kc, int K, int tid) {
#pragma unroll
    for (int j = 0; j < 4; j++) {
        int v = tid + j * 256;
        int row = v >> 3, c = v & 7;
        uint32_t off = SWZ128((uint32_t)(row * 128 + c * 16));
        CP16(st + off, Ae + (size_t)row * K + kc + c * 8);
    }
#pragma unroll
    for (int j = 0; j < 4; j++) {
        int v = tid + j * 256;
        int row = v >> 3, c = v & 7;
        uint32_t off = SWZ128((uint32_t)(row * 128 + c * 16));
        CP16(st + 16384u + off, Be + (size_t)row * K + kc + c * 8);
    }
}

// ---------------- HMMA GEMM (R10 champion mainloop) ----------------
template <int K_DIM, bool GELU>
__global__ void __launch_bounds__(256, 2)
hmma_gemm_kernel(const __half* __restrict__ A, const __half* __restrict__ B,
                 const float* __restrict__ bias, void* __restrict__ Cout,
                 int Ntot) {
    constexpr int NC = K_DIM / BK;
    extern __shared__ char smem[];
    __shared__ float bs[BN];
    const uint32_t sb = smem_u32(smem);
    const int tid = threadIdx.x;
    const int lane = tid & 31;
    const int wid = tid >> 5;
    const int wm = wid & 1;
    const int wn = wid >> 1;
    const int e = blockIdx.z;
    const int m0 = blockIdx.y * BM;
    const int n0 = blockIdx.x * BN;

    const __half* Ae = A + ((size_t)(e * ROWS_E + m0)) * K_DIM;
    const __half* Be = B + ((size_t)e * Ntot + n0) * K_DIM;

    if (tid < BN) bs[tid] = __ldg(bias + (size_t)e * Ntot + n0 + tid);

    const int l15 = lane & 15;
    const int l16 = lane >> 4;
    uint32_t aAddr[4], bAddr[2];
#pragma unroll
    for (int mi = 0; mi < 4; mi++)
        aAddr[mi] = sb + SWZ128((uint32_t)((wm * 64 + mi * 16 + l15) * 128 + l16 * 16));
#pragma unroll
    for (int ni = 0; ni < 2; ni++)
        bAddr[ni] = sb + 16384u +
                    SWZ128((uint32_t)((wn * 32 + ni * 16 + l15) * 128 + l16 * 16));

    float acc[4][4][4];
#pragma unroll
    for (int i = 0; i < 4; i++)
#pragma unroll
        for (int j = 0; j < 4; j++)
#pragma unroll
            for (int k = 0; k < 4; k++) acc[i][j][k] = 0.f;

    // prologue: 2 stages
    load_stage(sb, Ae, Be, 0, K_DIM, tid);
    CP_COMMIT();
    load_stage(sb + STAGE_B, Ae, Be, BK, K_DIM, tid);
    CP_COMMIT();

#pragma unroll 1
    for (int i = 0; i < NC; i++) {
        CP_WAIT1();
        __syncthreads();
        {
            int nx = i + 2;
            if (nx < NC) {
                int sx = nx % STAGES;
                load_stage(sb + (uint32_t)sx * STAGE_B, Ae, Be, nx * BK, K_DIM, tid);
            }
        }
        CP_COMMIT();

        const uint32_t so = (uint32_t)(i % STAGES) * STAGE_B;
#pragma unroll
        for (int ks = 0; ks < 4; ks++) {
            const uint32_t xv = (uint32_t)ks * 32u;
            uint32_t a[4][4], bb[2][4];
#pragma unroll
            for (int mi = 0; mi < 4; mi++) ldsm4(a[mi], (aAddr[mi] + so) ^ xv);
#pragma unroll
            for (int ni = 0; ni < 2; ni++) ldsm4(bb[ni], (bAddr[ni] + so) ^ xv);
#pragma unroll
            for (int mi = 0; mi < 4; mi++) {
#pragma unroll
                for (int f = 0; f < 4; f++) {
                    int ni = f >> 1, ss = f & 1;
                    mma16816(acc[mi][f], a[mi], bb[ni][ss], bb[ni][ss + 2]);
                }
            }
        }
    }
    CP_WAIT0();
    __syncthreads();

    // ---------------- smem-staged epilogue ----------------
    const int rbase = wm * 64 + (lane >> 2);
    if (GELU) {
        __half* sC = (__half*)smem;          // [128][136] halfs
#pragma unroll
        for (int mi = 0; mi < 4; mi++) {
#pragma unroll
            for (int f = 0; f < 4; f++) {
                int cidx = wn * 32 + (f >> 1) * 16 + (f & 1) * 8 + (lane & 3) * 2;
                float b0v = bs[cidx], b1v = bs[cidx + 1];
                int r0 = rbase + mi * 16;
                *(__half2*)&sC[r0 * 136 + cidx] = __floats2half2_rn(
                    gelu_f(acc[mi][f][0] + b0v), gelu_f(acc[mi][f][1] + b1v));
                *(__half2*)&sC[(r0 + 8) * 136 + cidx] = __floats2half2_rn(
                    gelu_f(acc[mi][f][2] + b0v), gelu_f(acc[mi][f][3] + b1v));
            }
        }
        __syncthreads();
        __half* Ch = (__half*)Cout;
        for (int v = tid; v < 128 * 16; v += 256) {
            int row = v >> 4, seg = v & 15;
            *(uint4*)(Ch + (size_t)(e * ROWS_E + m0 + row) * Ntot + n0 + seg * 8) =
                *(const uint4*)&sC[row * 136 + seg * 8];
        }
    } else {
        float* sF = (float*)smem;            // [64][132] floats per pass
        float* Cf = (float*)Cout;
#pragma unroll
        for (int p = 0; p < 2; p++) {
            if (wm == p) {
#pragma unroll
                for (int mi = 0; mi < 4; mi++) {
#pragma unroll
                    for (int f = 0; f < 4; f++) {
                        int cidx = wn * 32 + (f >> 1) * 16 + (f & 1) * 8 + (lane & 3) * 2;
                        float b0v = bs[cidx], b1v = bs[cidx + 1];
                        int r0l = (lane >> 2) + mi * 16;
                        *(float2*)&sF[r0l * 132 + cidx] =
                            make_float2(acc[mi][f][0] + b0v, acc[mi][f][1] + b1v);
                        *(float2*)&sF[(r0l + 8) * 132 + cidx] =
                            make_float2(acc[mi][f][2] + b0v, acc[mi][f][3] + b1v);
                    }
                }
            }
            __syncthreads();
            for (int v = tid; v < 64 * 32; v += 256) {
                int row = v >> 5, seg = v & 31;
                *(uint4*)(Cf + (size_t)(e * ROWS_E + m0 + p * 64 + row) * Ntot +
                          n0 + seg * 4) = *(const uint4*)&sF[row * 132 + seg * 4];
            }
            __syncthreads();
        }
    }
}

// ---------------- weighted combine ----------------
__global__ void combine_kernel(float* __restrict__ out) {
    int tg = blockIdx.x;
    int g = tg >> 10;
    float4 acc = make_float4(0.f, 0.f, 0.f, 0.f);
#pragma unroll
    for (int k = 0; k < 2; k++) {
        int slot = g_tok_slot[tg * 2 + k];
        if (slot >= 0) {
            int e = g_tok_e[tg * 2 + k];
            float gv = g_tok_g[tg * 2 + k];
            const float4* row =
                (const float4*)(g_ye + ((size_t)(e * GG + g) * CAP + slot) * DD);
            float4 v = row[threadIdx.x];
            acc.x = fmaf(gv, v.x, acc.x);
            acc.y = fmaf(gv, v.y, acc.y);
            acc.z = fmaf(gv, v.z, acc.z);
            acc.w = fmaf(gv, v.w, acc.w);
        }
    }
    ((float4*)(out + (size_t)tg * DD))[threadIdx.x] = acc;
}

// ---------------- launch ----------------
extern "C" void kernel_launch(void* const* d_in, const int* in_sizes, int n_in,
                              void* d_out, int out_size) {
    const float* x  = (const float*)d_in[0];
    const float* wr = (const float*)d_in[1];
    const float* w1 = (const float*)d_in[2];
    const float* b1 = (const float*)d_in[3];
    const float* w2 = (const float*)d_in[4];
    const float* b2 = (const float*)d_in[5];
    float* out = (float*)d_out;

    __half *xe, *w1t, *w2t, *h;
    float* ye;
    cudaGetSymbolAddress((void**)&xe, g_xe);
    cudaGetSymbolAddress((void**)&w1t, g_w1t);
    cudaGetSymbolAddress((void**)&w2t, g_w2t);
    cudaGetSymbolAddress((void**)&h, g_h);
    cudaGetSymbolAddress((void**)&ye, g_ye);

    cudaFuncSetAttribute(hmma_gemm_kernel<1024, true>,
                         cudaFuncAttributeMaxDynamicSharedMemorySize, SMEM_GEMM);
    cudaFuncSetAttribute(hmma_gemm_kernel<4096, false>,
                         cudaFuncAttributeMaxDynamicSharedMemorySize, SMEM_GEMM);

    // One secondary stream + events, created once on the first (uncaptured)
    // correctness call and reused; identical GPU work per call.
    static cudaStream_t s1 = nullptr;
    static cudaEvent_t evFork = nullptr, evW1 = nullptr, evW2 = nullptr;
    if (s1 == nullptr) {
        cudaStreamCreateWithFlags(&s1, cudaStreamNonBlocking);
        cudaEventCreateWithFlags(&evFork, cudaEventDisableTiming);
        cudaEventCreateWithFlags(&evW1, cudaEventDisableTiming);
        cudaEventCreateWithFlags(&evW2, cudaEventDisableTiming);
    }

    // Fork: transposes on s1 run concurrently with router/scan/gather chain.
    cudaEventRecord(evFork, 0);
    cudaStreamWaitEvent(s1, evFork, 0);

    // s1: weight transposes (independent of token routing)
    transpose_half_kernel<1024, 4096>
        <<<dim3(4096 / 32, 1024 / 64, EE), dim3(32, 8), 0, s1>>>(w1, w1t);
    cudaEventRecord(evW1, s1);
    transpose_half_kernel<4096, 1024>
        <<<dim3(1024 / 32, 4096 / 64, EE), dim3(32, 8), 0, s1>>>(w2, w2t);
    cudaEventRecord(evW2, s1);

    // stream 0: routing chain
    router_kernel<<<NTOK / 8, 256>>>(x, wr);
    imp_kernel<<<GG, 256>>>();
    if (out_size > NTOK * DD) aux_kernel<<<1, 1>>>(out);
    scan_kernel<<<GG, 1024>>>();
    gather_kernel<<<SLOTS, 128>>>(x);

    // GEMM1 needs xe (stream 0) + w1t (s1)
    cudaStreamWaitEvent(0, evW1, 0);
    hmma_gemm_kernel<1024, true>
        <<<dim3(MM / BN, ROWS_E / BM, EE), 256, SMEM_GEMM>>>(
            xe, w1t, b1, h, MM);

    // GEMM2 needs h (stream 0) + w2t (s1)
    cudaStreamWaitEvent(0, evW2, 0);
    hmma_gemm_kernel<4096, false>
        <<<dim3(DD / BN, ROWS_E / BM, EE), 256, SMEM_GEMM>>>(
            h, w2t, b2, ye, DD);

    combine_kernel<<<NTOK, 256>>>(out);
}

// round 15
// speedup vs baseline: 1.0742x; 1.0042x over previous
#include <cuda_runtime.h>
#include <cuda_fp16.h>
#include <stdint.h>
#include <math.h>

// ---------------- problem constants ----------------
#define DD 1024
#define EE 8
#define MM 4096
#define GG 8
#define CAP 256
#define NTOK 8192
#define ROWS_E 2048
#define SLOTS 16384

// GEMM tiling: CTA 128x128, 8 warps of 64x32, BK=64, 3 stages, SW128 (R10)
#define BM 128
#define BN 128
#define BK 64
#define STAGES 3
#define STAGE_B 32768
#define SMEM_GEMM (STAGES * STAGE_B)   // 98304

#define SWZ128(o) ((o) ^ (((o) >> 3) & 0x70))

// ---------------- device scratch (static, allocation-free) ----------------
__device__ __align__(1024) float g_gates[NTOK * EE];
__device__ __align__(1024) int   g_tok_e[NTOK * 2];
__device__ __align__(1024) float g_tok_g[NTOK * 2];
__device__ __align__(1024) int   g_tok_slot[NTOK * 2];
__device__ __align__(1024) int   g_slot_token[SLOTS];
__device__ __align__(1024) float g_cv2[GG];
__device__ __align__(1024) __half g_xe[(size_t)SLOTS * DD];
__device__ __align__(1024) __half g_w1t[(size_t)EE * MM * DD];    // [E][M][D]
__device__ __align__(1024) __half g_w2t[(size_t)EE * DD * MM];    // [E][D][M]
__device__ __align__(1024) __half g_h[(size_t)SLOTS * MM];
__device__ __align__(1024) float g_ye[(size_t)SLOTS * DD];

// ---------------- PTX helpers (baseline PTX only) ----------------
__device__ __forceinline__ uint32_t smem_u32(const void* p) {
    uint32_t a;
    asm("{ .reg .u64 t; cvta.to.shared.u64 t, %1; cvt.u32.u64 %0, t; }"
        : "=r"(a) : "l"(p));
    return a;
}
#define CP16(dst, src) \
    asm volatile("cp.async.cg.shared.global [%0], [%1], 16;\n" :: "r"(dst), "l"(src))
#define CP_COMMIT() asm volatile("cp.async.commit_group;\n" ::: "memory")
#define CP_WAIT1()  asm volatile("cp.async.wait_group 1;\n" ::: "memory")
#define CP_WAIT0()  asm volatile("cp.async.wait_group 0;\n" ::: "memory")

__device__ __forceinline__ void ldsm4(uint32_t* r, uint32_t addr) {
    asm volatile("ldmatrix.sync.aligned.m8n8.x4.shared.b16 {%0,%1,%2,%3}, [%4];"
                 : "=r"(r[0]), "=r"(r[1]), "=r"(r[2]), "=r"(r[3]) : "r"(addr));
}
__device__ __forceinline__ void mma16816(float* d, const uint32_t* a,
                                         uint32_t b0, uint32_t b1) {
    asm volatile(
        "mma.sync.aligned.m16n8k16.row.col.f32.f16.f16.f32 "
        "{%0,%1,%2,%3}, {%4,%5,%6,%7}, {%8,%9}, {%0,%1,%2,%3};"
        : "+f"(d[0]), "+f"(d[1]), "+f"(d[2]), "+f"(d[3])
        : "r"(a[0]), "r"(a[1]), "r"(a[2]), "r"(a[3]), "r"(b0), "r"(b1));
}

// ---------------- router ----------------
__global__ void router_kernel(const float* __restrict__ x,
                              const float* __restrict__ wr) {
    int gwarp = (blockIdx.x * blockDim.x + threadIdx.x) >> 5;
    int lane = threadIdx.x & 31;
    if (gwarp >= NTOK) return;
    const float* xr = x + (size_t)gwarp * DD;
    float acc[EE];
#pragma unroll
    for (int e = 0; e < EE; e++) acc[e] = 0.f;
    for (int d = lane; d < DD; d += 32) {
        float xv = __ldg(xr + d);
        const float4* w4 = (const float4*)(wr + (size_t)d * EE);
        float4 w0 = __ldg(w4);
        float4 w1 = __ldg(w4 + 1);
        acc[0] = fmaf(xv, w0.x, acc[0]); acc[1] = fmaf(xv, w0.y, acc[1]);
        acc[2] = fmaf(xv, w0.z, acc[2]); acc[3] = fmaf(xv, w0.w, acc[3]);
        acc[4] = fmaf(xv, w1.x, acc[4]); acc[5] = fmaf(xv, w1.y, acc[5]);
        acc[6] = fmaf(xv, w1.z, acc[6]); acc[7] = fmaf(xv, w1.w, acc[7]);
    }
#pragma unroll
    for (int off = 16; off > 0; off >>= 1)
#pragma unroll
        for (int e = 0; e < EE; e++)
            acc[e] += __shfl_down_sync(0xffffffffu, acc[e], off);
    if (lane == 0) {
        float mx = acc[0];
#pragma unroll
        for (int e = 1; e < EE; e++) mx = fmaxf(mx, acc[e]);
        float gv[EE], s = 0.f;
#pragma unroll
        for (int e = 0; e < EE; e++) { gv[e] = expf(acc[e] - mx); s += gv[e]; }
        float inv = 1.f / s;
#pragma unroll
        for (int e = 0; e < EE; e++) { gv[e] *= inv; g_gates[gwarp * EE + e] = gv[e]; }
        int i0 = 0;
#pragma unroll
        for (int e = 1; e < EE; e++) if (acc[e] > acc[i0]) i0 = e;
        int i1 = (i0 == 0) ? 1 : 0;
#pragma unroll
        for (int e = 0; e < EE; e++) if (e != i0 && acc[e] > acc[i1]) i1 = e;
        g_tok_e[gwarp * 2 + 0] = i0;
        g_tok_e[gwarp * 2 + 1] = i1;
        g_tok_g[gwarp * 2 + 0] = gv[i0];
        g_tok_g[gwarp * 2 + 1] = gv[i1];
    }
}

// ---------------- importance / aux loss ----------------
__global__ void imp_kernel() {
    int g = blockIdx.x;
    int tid = threadIdx.x;
    float acc[EE];
#pragma unroll
    for (int e = 0; e < EE; e++) acc[e] = 0.f;
    for (int t = tid; t < 1024; t += 256) {
        const float* gp = g_gates + (size_t)(g * 1024 + t) * EE;
#pragma unroll
        for (int e = 0; e < EE; e++) acc[e] += gp[e];
    }
    __shared__ float sh[EE][256];
#pragma unroll
    for (int e = 0; e < EE; e++) sh[e][tid] = acc[e];
    __syncthreads();
    for (int off = 128; off > 0; off >>= 1) {
        if (tid < off)
#pragma unroll
            for (int e = 0; e < EE; e++) sh[e][tid] += sh[e][tid + off];
        __syncthreads();
    }
    if (tid == 0) {
        float mean = 0.f;
#pragma unroll
        for (int e = 0; e < EE; e++) mean += sh[e][0];
        mean *= (1.f / EE);
        float var = 0.f;
#pragma unroll
        for (int e = 0; e < EE; e++) { float d = sh[e][0] - mean; var += d * d; }
        var *= (1.f / EE);
        g_cv2[g] = var / (mean * mean);
    }
}

__global__ void aux_kernel(float* __restrict__ out) {
    float s = 0.f;
#pragma unroll
    for (int g = 0; g < GG; g++) s += g_cv2[g];
    out[(size_t)NTOK * DD] = s * (1.f / GG);
}

// ---------------- ballot-based deterministic capacity scan ----------------
__global__ void scan_kernel() {
    int g = blockIdx.x;
    int t = threadIdx.x;          // 1024
    int w = t >> 5, lane = t & 31;
    int tg = g * 1024 + t;
    int e0 = g_tok_e[tg * 2 + 0];
    int e1 = g_tok_e[tg * 2 + 1];
    __shared__ int warpcnt[32][8];
    __shared__ int warpbase[32][8];
    __shared__ int tot0[8];
    __shared__ int filled[8];
    unsigned lt = (1u << lane) - 1u;
    unsigned m[8];

#pragma unroll
    for (int e = 0; e < 8; e++) m[e] = __ballot_sync(0xffffffffu, e0 == e);
    if (lane < 8) warpcnt[w][lane] = __popc(m[lane]);
    int intra0 = __popc(m[e0] & lt);
    __syncthreads();
    if (t < 256) {
        int e = t >> 5, wi = lane;
        int val = warpcnt[wi][e];
        int incl = val;
#pragma unroll
        for (int off = 1; off < 32; off <<= 1) {
            int n = __shfl_up_sync(0xffffffffu, incl, off);
            if (wi >= off) incl += n;
        }
        warpbase[wi][e] = incl - val;
        if (wi == 31) tot0[e] = incl;
    }
    __syncthreads();
    int pos0 = warpbase[w][e0] + intra0;
    __syncthreads();

#pragma unroll
    for (int e = 0; e < 8; e++) m[e] = __ballot_sync(0xffffffffu, e1 == e);
    if (lane < 8) warpcnt[w][lane] = __popc(m[lane]);
    int intra1 = __popc(m[e1] & lt);
    __syncthreads();
    if (t < 256) {
        int e = t >> 5, wi = lane;
        int val = warpcnt[wi][e];
        int incl = val;
#pragma unroll
        for (int off = 1; off < 32; off <<= 1) {
            int n = __shfl_up_sync(0xffffffffu, incl, off);
            if (wi >= off) incl += n;
        }
        warpbase[wi][e] = incl - val;
        if (wi == 31) filled[e] = min(tot0[e] + incl, CAP);
    }
    __syncthreads();
    int pos1 = tot0[e1] + warpbase[w][e1] + intra1;

    int slot0 = (pos0 < CAP) ? pos0 : -1;
    int slot1 = (pos1 < CAP) ? pos1 : -1;
    g_tok_slot[tg * 2 + 0] = slot0;
    g_tok_slot[tg * 2 + 1] = slot1;
    if (slot0 >= 0) g_slot_token[(e0 * GG + g) * CAP + slot0] = tg;
    if (slot1 >= 0) g_slot_token[(e1 * GG + g) * CAP + slot1] = tg;
    __syncthreads();
    for (int idx = t; idx < EE * CAP; idx += 1024) {
        int e = idx / CAP, c = idx % CAP;
        if (c >= filled[e]) g_slot_token[(e * GG + g) * CAP + c] = -1;
    }
}

// ---------------- gather tokens -> fp16 expert buffers ----------------
__global__ void gather_kernel(const float* __restrict__ x) {
    int s_id = blockIdx.x;
    int tok = g_slot_token[s_id];
    int t = threadIdx.x;  // 128
    __half* dst = g_xe + (size_t)s_id * DD;
    if (tok >= 0) {
        const float4* src = (const float4*)(x + (size_t)tok * DD);
        float4 a = src[2 * t], b = src[2 * t + 1];
        __half h8[8];
        h8[0] = __float2half(a.x); h8[1] = __float2half(a.y);
        h8[2] = __float2half(a.z); h8[3] = __float2half(a.w);
        h8[4] = __float2half(b.x); h8[5] = __float2half(b.y);
        h8[6] = __float2half(b.z); h8[7] = __float2half(b.w);
        ((uint4*)dst)[t] = *(uint4*)h8;
    } else {
        ((uint4*)dst)[t] = make_uint4(0, 0, 0, 0);
    }
}

// -------- weight transpose + fp16 convert: in[e][R][C] -> out[e][C][R] -----
template <int R, int C>
__global__ void transpose_half_kernel(const float* __restrict__ in,
                                      __half* __restrict__ out) {
    __shared__ float tile[32][66];
    int e = blockIdx.z;
    int rb = blockIdx.y * 64, cb = blockIdx.x * 32;
    const float* ip = in + (size_t)e * R * C;
    __half* op = out + (size_t)e * C * R;
    int tx = threadIdx.x, ty = threadIdx.y;  // 32 x 8
#pragma unroll
    for (int j = 0; j < 8; j++) {
        int r = ty + j * 8;
        tile[tx][r] = ip[(size_t)(rb + r) * C + cb + tx];
    }
    __syncthreads();
#pragma unroll
    for (int j = 0; j < 4; j++) {
        int oc = ty + j * 8;
        float2 v = *(const float2*)&tile[oc][2 * tx];
        *(__half2*)&op[(size_t)(cb + oc) * R + rb + 2 * tx] =
            __floats2half2_rn(v.x, v.y);
    }
}

// ---------------- fast tanh-gelu ----------------
__device__ __forceinline__ float gelu_f(float v) {
    float u = 0.7978845608028654f * (v + 0.044715f * v * v * v);
    float ex = __expf(2.f * u);
    float th = 1.f - 2.f / (ex + 1.f);
    return 0.5f * v * (1.f + th);
}

// ------------- stage loader: A 128x64 + B 128x64 fp16, SW128 swizzle -------
__device__ __forceinline__ void load_stage(uint32_t st,
                                           const __half* __restrict__ Ae,
                                           const __half* __restrict__ Be,
                                           int kc, int K, int tid) {
#pragma unroll
    for (int j = 0; j < 4; j++) {
        int v = tid + j * 256;
        int row = v >> 3, c = v & 7;
        uint32_t off = SWZ128((uint32_t)(row * 128 + c * 16));
        CP16(st + off, Ae + (size_t)row * K + kc + c * 8);
    }
#pragma unroll
    for (int j = 0; j < 4; j++) {
        int v = tid + j * 256;
        int row = v >> 3, c = v & 7;
        uint32_t off = SWZ128((uint32_t)(row * 128 + c * 16));
        CP16(st + 16384u + off, Be + (size_t)row * K + kc + c * 8);
    }
}

// ---------------- HMMA GEMM (R10 champion mainloop) ----------------
template <int K_DIM, bool GELU>
__global__ void __launch_bounds__(256, 2)
hmma_gemm_kernel(const __half* __restrict__ A, const __half* __restrict__ B,
                 const float* __restrict__ bias, void* __restrict__ Cout,
                 int Ntot) {
    constexpr int NC = K_DIM / BK;
    extern __shared__ char smem[];
    __shared__ float bs[BN];
    const uint32_t sb = smem_u32(smem);
    const int tid = threadIdx.x;
    const int lane = tid & 31;
    const int wid = tid >> 5;
    const int wm = wid & 1;
    const int wn = wid >> 1;
    const int e = blockIdx.z;
    const int m0 = blockIdx.y * BM;
    const int n0 = blockIdx.x * BN;

    const __half* Ae = A + ((size_t)(e * ROWS_E + m0)) * K_DIM;
    const __half* Be = B + ((size_t)e * Ntot + n0) * K_DIM;

    if (tid < BN) bs[tid] = __ldg(bias + (size_t)e * Ntot + n0 + tid);

    const int l15 = lane & 15;
    const int l16 = lane >> 4;
    uint32_t aAddr[4], bAddr[2];
#pragma unroll
    for (int mi = 0; mi < 4; mi++)
        aAddr[mi] = sb + SWZ128((uint32_t)((wm * 64 + mi * 16 + l15) * 128 + l16 * 16));
#pragma unroll
    for (int ni = 0; ni < 2; ni++)
        bAddr[ni] = sb + 16384u +
                    SWZ128((uint32_t)((wn * 32 + ni * 16 + l15) * 128 + l16 * 16));

    float acc[4][4][4];
#pragma unroll
    for (int i = 0; i < 4; i++)
#pragma unroll
        for (int j = 0; j < 4; j++)
#pragma unroll
            for (int k = 0; k < 4; k++) acc[i][j][k] = 0.f;

    // prologue: 2 stages
    load_stage(sb, Ae, Be, 0, K_DIM, tid);
    CP_COMMIT();
    load_stage(sb + STAGE_B, Ae, Be, BK, K_DIM, tid);
    CP_COMMIT();

#pragma unroll 1
    for (int i = 0; i < NC; i++) {
        CP_WAIT1();
        __syncthreads();
        {
            int nx = i + 2;
            if (nx < NC) {
                int sx = nx % STAGES;
                load_stage(sb + (uint32_t)sx * STAGE_B, Ae, Be, nx * BK, K_DIM, tid);
            }
        }
        CP_COMMIT();

        const uint32_t so = (uint32_t)(i % STAGES) * STAGE_B;
#pragma unroll
        for (int ks = 0; ks < 4; ks++) {
            const uint32_t xv = (uint32_t)ks * 32u;
            uint32_t a[4][4], bb[2][4];
#pragma unroll
            for (int mi = 0; mi < 4; mi++) ldsm4(a[mi], (aAddr[mi] + so) ^ xv);
#pragma unroll
            for (int ni = 0; ni < 2; ni++) ldsm4(bb[ni], (bAddr[ni] + so) ^ xv);
#pragma unroll
            for (int mi = 0; mi < 4; mi++) {
#pragma unroll
                for (int f = 0; f < 4; f++) {
                    int ni = f >> 1, ss = f & 1;
                    mma16816(acc[mi][f], a[mi], bb[ni][ss], bb[ni][ss + 2]);
                }
            }
        }
    }
    CP_WAIT0();
    __syncthreads();

    // ---------------- smem-staged epilogue ----------------
    const int rbase = wm * 64 + (lane >> 2);
    if (GELU) {
        __half* sC = (__half*)smem;          // [128][136] halfs
#pragma unroll
        for (int mi = 0; mi < 4; mi++) {
#pragma unroll
            for (int f = 0; f < 4; f++) {
                int cidx = wn * 32 + (f >> 1) * 16 + (f & 1) * 8 + (lane & 3) * 2;
                float b0v = bs[cidx], b1v = bs[cidx + 1];
                int r0 = rbase + mi * 16;
                *(__half2*)&sC[r0 * 136 + cidx] = __floats2half2_rn(
                    gelu_f(acc[mi][f][0] + b0v), gelu_f(acc[mi][f][1] + b1v));
                *(__half2*)&sC[(r0 + 8) * 136 + cidx] = __floats2half2_rn(
                    gelu_f(acc[mi][f][2] + b0v), gelu_f(acc[mi][f][3] + b1v));
            }
        }
        __syncthreads();
        __half* Ch = (__half*)Cout;
        for (int v = tid; v < 128 * 16; v += 256) {
            int row = v >> 4, seg = v & 15;
            *(uint4*)(Ch + (size_t)(e * ROWS_E + m0 + row) * Ntot + n0 + seg * 8) =
                *(const uint4*)&sC[row * 136 + seg * 8];
        }
    } else {
        float* sF = (float*)smem;            // [64][132] floats per pass
        float* Cf = (float*)Cout;
#pragma unroll
        for (int p = 0; p < 2; p++) {
            if (wm == p) {
#pragma unroll
                for (int mi = 0; mi < 4; mi++) {
#pragma unroll
                    for (int f = 0; f < 4; f++) {
                        int cidx = wn * 32 + (f >> 1) * 16 + (f & 1) * 8 + (lane & 3) * 2;
                        float b0v = bs[cidx], b1v = bs[cidx + 1];
                        int r0l = (lane >> 2) + mi * 16;
                        *(float2*)&sF[r0l * 132 + cidx] =
                            make_float2(acc[mi][f][0] + b0v, acc[mi][f][1] + b1v);
                        *(float2*)&sF[(r0l + 8) * 132 + cidx] =
                            make_float2(acc[mi][f][2] + b0v, acc[mi][f][3] + b1v);
                    }
                }
            }
            __syncthreads();
            for (int v = tid; v < 64 * 32; v += 256) {
                int row = v >> 5, seg = v & 31;
                *(uint4*)(Cf + (size_t)(e * ROWS_E + m0 + p * 64 + row) * Ntot +
                          n0 + seg * 4) = *(const uint4*)&sF[row * 132 + seg * 4];
            }
            __syncthreads();
        }
    }
}

// ---------------- weighted combine ----------------
__global__ void combine_kernel(float* __restrict__ out) {
    int tg = blockIdx.x;
    int g = tg >> 10;
    float4 acc = make_float4(0.f, 0.f, 0.f, 0.f);
#pragma unroll
    for (int k = 0; k < 2; k++) {
        int slot = g_tok_slot[tg * 2 + k];
        if (slot >= 0) {
            int e = g_tok_e[tg * 2 + k];
            float gv = g_tok_g[tg * 2 + k];
            const float4* row =
                (const float4*)(g_ye + ((size_t)(e * GG + g) * CAP + slot) * DD);
            float4 v = row[threadIdx.x];
            acc.x = fmaf(gv, v.x, acc.x);
            acc.y = fmaf(gv, v.y, acc.y);
            acc.z = fmaf(gv, v.z, acc.z);
            acc.w = fmaf(gv, v.w, acc.w);
        }
    }
    ((float4*)(out + (size_t)tg * DD))[threadIdx.x] = acc;
}

// ---------------- launch ----------------
extern "C" void kernel_launch(void* const* d_in, const int* in_sizes, int n_in,
                              void* d_out, int out_size) {
    const float* x  = (const float*)d_in[0];
    const float* wr = (const float*)d_in[1];
    const float* w1 = (const float*)d_in[2];
    const float* b1 = (const float*)d_in[3];
    const float* w2 = (const float*)d_in[4];
    const float* b2 = (const float*)d_in[5];
    float* out = (float*)d_out;

    __half *xe, *w1t, *w2t, *h;
    float* ye;
    cudaGetSymbolAddress((void**)&xe, g_xe);
    cudaGetSymbolAddress((void**)&w1t, g_w1t);
    cudaGetSymbolAddress((void**)&w2t, g_w2t);
    cudaGetSymbolAddress((void**)&h, g_h);
    cudaGetSymbolAddress((void**)&ye, g_ye);

    cudaFuncSetAttribute(hmma_gemm_kernel<1024, true>,
                         cudaFuncAttributeMaxDynamicSharedMemorySize, SMEM_GEMM);
    cudaFuncSetAttribute(hmma_gemm_kernel<4096, false>,
                         cudaFuncAttributeMaxDynamicSharedMemorySize, SMEM_GEMM);

    // Streams/events created once on the first (uncaptured) correctness call
    // and reused; identical GPU work per call (graph-capture safe fork-join).
    static cudaStream_t s1 = nullptr;
    static cudaEvent_t evFork = nullptr, evW1 = nullptr, evW2 = nullptr;
    static cudaEvent_t evR = nullptr, evAux = nullptr;
    if (s1 == nullptr) {
        cudaStreamCreateWithFlags(&s1, cudaStreamNonBlocking);
        cudaEventCreateWithFlags(&evFork, cudaEventDisableTiming);
        cudaEventCreateWithFlags(&evW1, cudaEventDisableTiming);
        cudaEventCreateWithFlags(&evW2, cudaEventDisableTiming);
        cudaEventCreateWithFlags(&evR, cudaEventDisableTiming);
        cudaEventCreateWithFlags(&evAux, cudaEventDisableTiming);
    }

    // Fork: transposes + (imp,aux) on s1 run concurrently with the
    // router->scan->gather->GEMM chain on stream 0.
    cudaEventRecord(evFork, 0);
    cudaStreamWaitEvent(s1, evFork, 0);

    // s1: weight transposes (independent of token routing)
    transpose_half_kernel<1024, 4096>
        <<<dim3(4096 / 32, 1024 / 64, EE), dim3(32, 8), 0, s1>>>(w1, w1t);
    cudaEventRecord(evW1, s1);
    transpose_half_kernel<4096, 1024>
        <<<dim3(1024 / 32, 4096 / 64, EE), dim3(32, 8), 0, s1>>>(w2, w2t);
    cudaEventRecord(evW2, s1);

    // stream 0: routing chain (imp/aux moved off the critical path)
    router_kernel<<<NTOK / 8, 256>>>(x, wr);
    cudaEventRecord(evR, 0);
    scan_kernel<<<GG, 1024>>>();
    gather_kernel<<<SLOTS, 128>>>(x);

    // s1: aux-loss chain (depends only on router output)
    cudaStreamWaitEvent(s1, evR, 0);
    imp_kernel<<<GG, 256, 0, s1>>>();
    if (out_size > NTOK * DD) aux_kernel<<<1, 1, 0, s1>>>(out);
    cudaEventRecord(evAux, s1);

    // GEMM1 needs xe (stream 0) + w1t (s1)
    cudaStreamWaitEvent(0, evW1, 0);
    hmma_gemm_kernel<1024, true>
        <<<dim3(MM / BN, ROWS_E / BM, EE), 256, SMEM_GEMM>>>(
            xe, w1t, b1, h, MM);

    // GEMM2 needs h (stream 0) + w2t (s1)
    cudaStreamWaitEvent(0, evW2, 0);
    hmma_gemm_kernel<4096, false>
        <<<dim3(DD / BN, ROWS_E / BM, EE), 256, SMEM_GEMM>>>(
            h, w2t, b2, ye, DD);

    // Join aux chain back into stream 0 before the final kernel.
    cudaStreamWaitEvent(0, evAux, 0);
    combine_kernel<<<NTOK, 256>>>(out);
}